// round 7
// baseline (speedup 1.0000x reference)
#include <cuda_runtime.h>
#include <cuda_fp16.h>
#include <math.h>
#include <cstdint>

#define NTOK 16384
#define DDIM 512
#define NEXP 16
#define TOPK 2
#define EMBD 128
#define HID  1024
#define HID2 512
#define PAD_ROWS (NTOK*TOPK + NEXP*128)   // 34816

// ---------------- device scratch ----------------
__device__ int    g_counts[NEXP];
__device__ int    g_offsets[NEXP+1];
__device__ int    g_cursor[NEXP];
__device__ int    g_top2[NTOK*TOPK];
__device__ float  g_gates[NTOK*TOPK];
__device__ int    g_slot[NTOK*TOPK];
__device__ int    g_rowtok[PAD_ROWS];
__device__ __half g_inph[(size_t)NTOK*DDIM];       // inputs fp16 [N][D]
__device__ __half g_w1h[(size_t)NEXP*DDIM*HID];    // W1 fp16 [E][D][H]  (native layout)
__device__ __half g_w2h[(size_t)NEXP*HID*HID2];    // W2 fp16 [E][H][H2]
__device__ __half g_w3h[(size_t)NEXP*HID2*DDIM];   // W3 fp16 [E][H2][D]
__device__ __half g_h1h[(size_t)PAD_ROWS*HID];
__device__ __half g_h2h[(size_t)PAD_ROWS*HID2];
__device__ float  g_o3[(size_t)PAD_ROWS*DDIM];

// ---------------- helpers ----------------
__device__ __forceinline__ uint32_t smem_u32(const void* p){
    uint32_t a;
    asm("{ .reg .u64 t; cvta.to.shared.u64 t, %1; cvt.u32.u64 %0, t; }" : "=r"(a) : "l"(p));
    return a;
}
__device__ __forceinline__ void cp16(uint32_t dst, const void* src){
    asm volatile("cp.async.cg.shared.global [%0], [%1], 16;" :: "r"(dst), "l"(src) : "memory");
}
__device__ __forceinline__ void cp_commit(){ asm volatile("cp.async.commit_group;" ::: "memory"); }
template<int N> __device__ __forceinline__ void cp_wait(){
    asm volatile("cp.async.wait_group %0;" :: "n"(N) : "memory");
}
__device__ __forceinline__ void ldsm4(uint32_t& r0, uint32_t& r1, uint32_t& r2, uint32_t& r3, uint32_t addr){
    asm volatile("ldmatrix.sync.aligned.m8n8.x4.shared.b16 {%0,%1,%2,%3}, [%4];"
        : "=r"(r0), "=r"(r1), "=r"(r2), "=r"(r3) : "r"(addr));
}
__device__ __forceinline__ void ldsm4t(uint32_t& r0, uint32_t& r1, uint32_t& r2, uint32_t& r3, uint32_t addr){
    asm volatile("ldmatrix.sync.aligned.m8n8.x4.trans.shared.b16 {%0,%1,%2,%3}, [%4];"
        : "=r"(r0), "=r"(r1), "=r"(r2), "=r"(r3) : "r"(addr));
}
__device__ __forceinline__ void mma16816(float* c, uint32_t a0, uint32_t a1, uint32_t a2, uint32_t a3,
                                         uint32_t b0, uint32_t b1){
    asm volatile("mma.sync.aligned.m16n8k16.row.col.f32.f16.f16.f32 "
        "{%0,%1,%2,%3}, {%4,%5,%6,%7}, {%8,%9}, {%0,%1,%2,%3};"
        : "+f"(c[0]), "+f"(c[1]), "+f"(c[2]), "+f"(c[3])
        : "r"(a0), "r"(a1), "r"(a2), "r"(a3), "r"(b0), "r"(b1));
}

// ---------------- weight fp32->fp16 convert (native layout) + zero counts ----------------
#define W1_ELEMS ((size_t)NEXP*DDIM*HID)    // 8388608
#define W2_ELEMS ((size_t)NEXP*HID*HID2)    // 8388608
#define W3_ELEMS ((size_t)NEXP*HID2*DDIM)   // 4194304
#define WTOT4 ((W1_ELEMS + W2_ELEMS + W3_ELEMS) / 4)   // 5242880

__global__ void convw_kernel(const float* __restrict__ W1, const float* __restrict__ W2,
                             const float* __restrict__ W3){
    if (blockIdx.x == 0 && threadIdx.x < NEXP) g_counts[threadIdx.x] = 0;
    size_t i = ((size_t)blockIdx.x * blockDim.x + threadIdx.x) * 4;
    const float* src; __half* dst;
    if (i < W1_ELEMS)                 { src = W1 + i;                     dst = g_w1h + i; }
    else if (i < W1_ELEMS + W2_ELEMS) { src = W2 + (i - W1_ELEMS);        dst = g_w2h + (i - W1_ELEMS); }
    else                              { src = W3 + (i - W1_ELEMS - W2_ELEMS); dst = g_w3h + (i - W1_ELEMS - W2_ELEMS); }
    float4 v = *(const float4*)src;
    __half2 h0 = __floats2half2_rn(v.x, v.y);
    __half2 h1 = __floats2half2_rn(v.z, v.w);
    *(uint2*)dst = make_uint2(*(uint32_t*)&h0, *(uint32_t*)&h1);
}

// ---------------- fp16 mma.sync GEMM: C[M,Nout] = A @ W[e] + bias[e] ----------------
// A: [rows][K] fp16 (gathered for stage 1), B: [E][K][Nout] fp16 native layout.
// BM=128, BN=128, BK=64, 256 threads (8 warps as 2m x 4n), warp tile 64x32.
// A smem [m][k]: rows 64 halves padded to 72 (144B). B smem [k][n]: rows 128 halves padded to 136 (272B).
// B fragments via ldmatrix.x4.trans. 2-stage double buffer, dynamic smem.
#define LDA_H 72
#define LDB_H 136
#define A_REGION 18432                // 128 * 144
#define B_REG_OFF A_REGION
#define BUF_BYTES (18432 + 17408)     // + B region: 64*272 = 35840
#define GSMEM_BYTES (2 * BUF_BYTES)   // 71680

template<bool GATHER, bool EXPERT, bool HALF_RELU_OUT>
__global__ void __launch_bounds__(256, 2)
gemm_mma(const __half* __restrict__ A, const __half* __restrict__ Bw,
         const float* __restrict__ bias, void* __restrict__ Cout,
         int K, int Nout)
{
    extern __shared__ __align__(16) char smem[];
    const uint32_t sb = smem_u32(smem);

    const int t = threadIdx.x, wid = t >> 5, l = t & 31;
    const int m0 = blockIdx.y * 128, n0 = blockIdx.x * 128;
    const int wm = wid >> 2, wn = wid & 3;          // 2 x 4 warps

    int e = 0;
    if (EXPERT) {
        #pragma unroll
        for (int i = 0; i < NEXP-1; i++) if (g_offsets[i+1] <= m0) e = i + 1;
    }
    const __half* Bb = Bw + (size_t)e * K * Nout;
    const float*  bb = bias + (size_t)e * Nout;

    // ---- A loader: row = t>>1 (2 threads/row), each thread 4 x 16B chunks ----
    const int arow = t >> 1, ahalf = t & 1;
    int tok = GATHER ? g_rowtok[m0 + arow] : (m0 + arow);
    const __half* asrc = A + (size_t)tok * K + ahalf * 32;    // 4 chunks of 8 halves
    const uint32_t adst = arow * 144 + ahalf * 64;

    // ---- B loader: krow = t>>2 (4 threads/row), each thread 4 x 16B chunks ----
    const int bkrow = t >> 2, bch = t & 3;
    const __half* bsrc = Bb + (size_t)bkrow * Nout + n0 + bch * 32;
    const uint32_t bdst = B_REG_OFF + bkrow * 272 + bch * 64;

    // ---- ldmatrix lane addressing (byte offsets within a buffer) ----
    uint32_t a_off[4], b_off[2];
    {
        int a_lrow = l & 15, a_lcol = (l >> 4) * 8;
        #pragma unroll
        for (int mt = 0; mt < 4; mt++)
            a_off[mt] = ((wm*64 + mt*16 + a_lrow) * LDA_H + a_lcol) * 2;
        int b_krow = l & 15, b_ncol = (l >> 4) * 8;
        #pragma unroll
        for (int p = 0; p < 2; p++)
            b_off[p] = B_REG_OFF + (b_krow * LDB_H + wn*32 + p*16 + b_ncol) * 2;
    }

    float acc[4][4][4];
    #pragma unroll
    for (int i = 0; i < 4; i++)
        #pragma unroll
        for (int j = 0; j < 4; j++)
            #pragma unroll
            for (int r = 0; r < 4; r++) acc[i][j][r] = 0.f;

    const int C = K >> 6;

    auto load_tile = [&](int c){
        const int kb = c * 64;
        const uint32_t base = sb + (uint32_t)(c & 1) * BUF_BYTES;
        #pragma unroll
        for (int j = 0; j < 4; j++)
            cp16(base + adst + j*16, asrc + kb + j*8);
        #pragma unroll
        for (int j = 0; j < 4; j++)
            cp16(base + bdst + j*16, bsrc + (size_t)kb * Nout + j*8);
        cp_commit();
    };

    load_tile(0);

    for (int c = 0; c < C; c++) {
        if (c + 1 < C) { load_tile(c + 1); cp_wait<1>(); }
        else           { cp_wait<0>(); }
        __syncthreads();

        const uint32_t base = sb + (uint32_t)(c & 1) * BUF_BYTES;
        #pragma unroll
        for (int ks = 0; ks < 4; ks++) {
            uint32_t a[4][4], b[2][4];
            #pragma unroll
            for (int mt = 0; mt < 4; mt++)
                ldsm4(a[mt][0], a[mt][1], a[mt][2], a[mt][3], base + a_off[mt] + ks*32);
            #pragma unroll
            for (int p = 0; p < 2; p++)
                ldsm4t(b[p][0], b[p][1], b[p][2], b[p][3], base + b_off[p] + ks*16*LDB_H*2);
            #pragma unroll
            for (int mt = 0; mt < 4; mt++)
                #pragma unroll
                for (int nt = 0; nt < 4; nt++)
                    mma16816(acc[mt][nt], a[mt][0], a[mt][1], a[mt][2], a[mt][3],
                             b[nt>>1][(nt&1)*2], b[nt>>1][(nt&1)*2+1]);
        }
        __syncthreads();
    }

    // ---- epilogue ----
    const int grp = l >> 2, tig = l & 3;
    #pragma unroll
    for (int mt = 0; mt < 4; mt++) {
        const int row = m0 + wm*64 + mt*16 + grp;
        #pragma unroll
        for (int nt = 0; nt < 4; nt++) {
            const int col = n0 + wn*32 + nt*8 + tig*2;
            float bv0 = bb[col], bv1 = bb[col+1];
            float v0 = acc[mt][nt][0] + bv0, v1 = acc[mt][nt][1] + bv1;
            float v2 = acc[mt][nt][2] + bv0, v3 = acc[mt][nt][3] + bv1;
            if (HALF_RELU_OUT) {
                v0 = fmaxf(v0, 0.f); v1 = fmaxf(v1, 0.f);
                v2 = fmaxf(v2, 0.f); v3 = fmaxf(v3, 0.f);
                __half2 h0 = __floats2half2_rn(v0, v1);
                __half2 h1 = __floats2half2_rn(v2, v3);
                *(uint32_t*)((__half*)Cout + (size_t)row     * Nout + col) = *(uint32_t*)&h0;
                *(uint32_t*)((__half*)Cout + (size_t)(row+8) * Nout + col) = *(uint32_t*)&h1;
            } else {
                *(float2*)((float*)Cout + (size_t)row     * Nout + col) = make_float2(v0, v1);
                *(float2*)((float*)Cout + (size_t)(row+8) * Nout + col) = make_float2(v2, v3);
            }
        }
    }
}

// ---------------- router SIMT fp32 GEMM (exact; feeds top-k), BM=64 + fp16 input emit ----------------
__global__ void __launch_bounds__(256, 2)
router_gemm64(const float* __restrict__ A, const float* __restrict__ W,
              const float* __restrict__ bias, float* __restrict__ C)
{
    const int m0 = blockIdx.x * 64;

    __shared__ float As[16][64];
    __shared__ float Bs[16][128];

    const int t  = threadIdx.x;
    const int tx = t & 15;       // col group (8 cols)
    const int ty = t >> 4;       // row group (4 rows)

    const int am = t >> 2, aj = t & 3;
    const int arowi = m0 + am;
    const float* arow = A + (size_t)arowi * DDIM + aj * 4;
    __half* hdst = g_inph + (size_t)arowi * DDIM + aj * 4;

    const int bk = t >> 5;
    const int bn = (t & 31) * 4;
    const float* brow0 = W + (size_t)bk       * EMBD + bn;
    const float* brow1 = W + (size_t)(bk + 8) * EMBD + bn;

    float acc[4][8];
    #pragma unroll
    for (int i = 0; i < 4; i++)
        #pragma unroll
        for (int j = 0; j < 8; j++) acc[i][j] = 0.f;

    for (int kb = 0; kb < DDIM; kb += 16) {
        float4 a0 = *(const float4*)(arow + kb);
        float4 b0 = *(const float4*)(brow0 + (size_t)kb * EMBD);
        float4 b1 = *(const float4*)(brow1 + (size_t)kb * EMBD);

        {
            __half2 h0 = __floats2half2_rn(a0.x, a0.y);
            __half2 h1 = __floats2half2_rn(a0.z, a0.w);
            *(uint2*)(hdst + kb) = make_uint2(*(uint32_t*)&h0, *(uint32_t*)&h1);
        }

        As[aj*4+0][am] = a0.x; As[aj*4+1][am] = a0.y;
        As[aj*4+2][am] = a0.z; As[aj*4+3][am] = a0.w;
        *(float4*)&Bs[bk][bn]   = b0;
        *(float4*)&Bs[bk+8][bn] = b1;
        __syncthreads();

        #pragma unroll
        for (int k = 0; k < 16; k++) {
            float4 av  = *(const float4*)&As[k][ty*4];
            float4 bv0 = *(const float4*)&Bs[k][tx*8];
            float4 bv1 = *(const float4*)&Bs[k][tx*8+4];
            float a[4] = {av.x, av.y, av.z, av.w};
            float b[8] = {bv0.x, bv0.y, bv0.z, bv0.w, bv1.x, bv1.y, bv1.z, bv1.w};
            #pragma unroll
            for (int i = 0; i < 4; i++)
                #pragma unroll
                for (int j = 0; j < 8; j++)
                    acc[i][j] = fmaf(a[i], b[j], acc[i][j]);
        }
        __syncthreads();
    }

    #pragma unroll
    for (int i = 0; i < 4; i++) {
        float* crow = C + (size_t)(m0 + ty*4 + i) * EMBD + tx*8;
        float4 v0, v1;
        v0.x = acc[i][0] + bias[tx*8+0]; v0.y = acc[i][1] + bias[tx*8+1];
        v0.z = acc[i][2] + bias[tx*8+2]; v0.w = acc[i][3] + bias[tx*8+3];
        v1.x = acc[i][4] + bias[tx*8+4]; v1.y = acc[i][5] + bias[tx*8+5];
        v1.z = acc[i][6] + bias[tx*8+6]; v1.w = acc[i][7] + bias[tx*8+7];
        *(float4*)crow       = v0;
        *(float4*)(crow + 4) = v1;
    }
}

// ---------------- gating / scatter / combine ----------------
__global__ void gating_kernel(const float* __restrict__ q,
                              const float* __restrict__ emb,
                              float* __restrict__ probs_out)
{
    int gw   = (blockIdx.x * blockDim.x + threadIdx.x) >> 5;
    int lane = threadIdx.x & 31;
    if (gw >= NTOK) return;

    const float* qr = q + (size_t)gw * EMBD;
    float qv[4];
    #pragma unroll
    for (int u = 0; u < 4; u++) qv[u] = qr[lane + 32*u];

    float sc[NEXP];
    #pragma unroll
    for (int e = 0; e < NEXP; e++) {
        float d = 0.f;
        #pragma unroll
        for (int u = 0; u < 4; u++) {
            float diff = qv[u] - emb[e*EMBD + lane + 32*u];
            d = fmaf(diff, diff, d);
        }
        #pragma unroll
        for (int o = 16; o > 0; o >>= 1) d += __shfl_xor_sync(0xffffffffu, d, o);
        sc[e] = -d;
    }

    float mx = sc[0];
    #pragma unroll
    for (int e = 1; e < NEXP; e++) mx = fmaxf(mx, sc[e]);
    float ex[NEXP]; float sum = 0.f;
    #pragma unroll
    for (int e = 0; e < NEXP; e++) { ex[e] = expf(sc[e] - mx); sum += ex[e]; }
    float inv = 1.f / sum;
    #pragma unroll
    for (int e = 0; e < NEXP; e++)
        if (lane == e) probs_out[(size_t)gw*NEXP + e] = ex[e] * inv;

    int i0 = 0; float v0 = sc[0];
    #pragma unroll
    for (int e = 1; e < NEXP; e++) if (sc[e] > v0) { v0 = sc[e]; i0 = e; }
    int i1 = -1; float v1 = -INFINITY;
    #pragma unroll
    for (int e = 0; e < NEXP; e++) if (e != i0 && sc[e] > v1) { v1 = sc[e]; i1 = e; }

    if (lane == 0) {
        float e1 = expf(v1 - v0);
        float s  = 1.f + e1;
        g_top2[gw*2]    = i0; g_top2[gw*2+1]  = i1;
        g_gates[gw*2]   = 1.f / s; g_gates[gw*2+1] = e1 / s;
        atomicAdd(&g_counts[i0], 1);
        atomicAdd(&g_counts[i1], 1);
    }
}

__global__ void offsets_kernel() {
    if (threadIdx.x == 0) {
        int off = 0;
        for (int e = 0; e < NEXP; e++) {
            g_offsets[e] = off;
            g_cursor[e]  = off;
            off += (g_counts[e] + 127) & ~127;
        }
        g_offsets[NEXP] = off;
    }
}

__global__ void scatter_kernel() {
    int i = blockIdx.x * blockDim.x + threadIdx.x;
    if (i < NTOK*TOPK) {
        int e   = g_top2[i];
        int pos = atomicAdd(&g_cursor[e], 1);
        g_rowtok[pos] = i >> 1;
        g_slot[i]     = pos;
    }
}

__global__ void combine_kernel(float* __restrict__ out)
{
    int n = blockIdx.x;
    int t = threadIdx.x;
    int s0 = g_slot[2*n], s1 = g_slot[2*n+1];
    float g0 = g_gates[2*n], g1 = g_gates[2*n+1];
    const float4* r0 = (const float4*)(g_o3 + (size_t)s0 * DDIM);
    const float4* r1 = (const float4*)(g_o3 + (size_t)s1 * DDIM);
    float4 a = r0[t], b = r1[t];
    float4 v;
    v.x = g0*a.x + g1*b.x; v.y = g0*a.y + g1*b.y;
    v.z = g0*a.z + g1*b.z; v.w = g0*a.w + g1*b.w;
    ((float4*)(out + (size_t)n * DDIM))[t] = v;
}

// ---------------- launch ----------------
extern "C" void kernel_launch(void* const* d_in, const int* in_sizes, int n_in,
                              void* d_out, int out_size)
{
    const float* inputs    = (const float*)d_in[0];
    const float* router_W  = (const float*)d_in[1];
    const float* router_b  = (const float*)d_in[2];
    const float* expert_emb= (const float*)d_in[3];
    const float* W1 = (const float*)d_in[4];
    const float* b1 = (const float*)d_in[5];
    const float* W2 = (const float*)d_in[6];
    const float* b2 = (const float*)d_in[7];
    const float* W3 = (const float*)d_in[8];
    const float* b3 = (const float*)d_in[9];

    float* out       = (float*)d_out;
    float* out_comb  = out;
    float* out_q     = out + (size_t)NTOK * DDIM;
    float* out_probs = out + (size_t)NTOK * DDIM + (size_t)NTOK * EMBD;

    __half *inph, *w1h, *w2h, *w3h, *h1h, *h2h;
    float *o3p;
    cudaGetSymbolAddress((void**)&inph, g_inph);
    cudaGetSymbolAddress((void**)&w1h,  g_w1h);
    cudaGetSymbolAddress((void**)&w2h,  g_w2h);
    cudaGetSymbolAddress((void**)&w3h,  g_w3h);
    cudaGetSymbolAddress((void**)&h1h,  g_h1h);
    cudaGetSymbolAddress((void**)&h2h,  g_h2h);
    cudaGetSymbolAddress((void**)&o3p,  g_o3);

    cudaFuncSetAttribute(gemm_mma<true,true,true>,   cudaFuncAttributeMaxDynamicSharedMemorySize, GSMEM_BYTES);
    cudaFuncSetAttribute(gemm_mma<false,true,true>,  cudaFuncAttributeMaxDynamicSharedMemorySize, GSMEM_BYTES);
    cudaFuncSetAttribute(gemm_mma<false,true,false>, cudaFuncAttributeMaxDynamicSharedMemorySize, GSMEM_BYTES);

    // launch 0: weight convert (+ zero counts)
    convw_kernel<<<(unsigned)(WTOT4/256), 256>>>(W1, W2, W3);
    // launch 1: router fp32 (exact; also emits fp16 inputs)
    router_gemm64<<<NTOK/64, 256>>>(inputs, router_W, router_b, out_q);
    // launch 2-4: gating, offsets, scatter
    gating_kernel<<<(NTOK*32)/256, 256>>>(out_q, expert_emb, out_probs);
    offsets_kernel<<<1, 32>>>();
    scatter_kernel<<<(NTOK*TOPK + 255)/256, 256>>>();

    // launch 5-7: expert MLP on tensor cores (fp16 mma.sync, BK=64, double buffered)
    gemm_mma<true,true,true><<<dim3(HID/128,  PAD_ROWS/128), 256, GSMEM_BYTES>>>(
        inph, w1h, b1, h1h, DDIM, HID);
    gemm_mma<false,true,true><<<dim3(HID2/128, PAD_ROWS/128), 256, GSMEM_BYTES>>>(
        h1h, w2h, b2, h2h, HID, HID2);
    gemm_mma<false,true,false><<<dim3(DDIM/128, PAD_ROWS/128), 256, GSMEM_BYTES>>>(
        h2h, w3h, b3, o3p, HID2, DDIM);

    combine_kernel<<<NTOK, 128>>>(out_comb);
}

// round 10
// speedup vs baseline: 1.2966x; 1.2966x over previous
#include <cuda_runtime.h>
#include <cuda_fp16.h>
#include <math.h>
#include <cstdint>

#define NTOK 16384
#define DDIM 512
#define NEXP 16
#define TOPK 2
#define EMBD 128
#define HID  1024
#define HID2 512
#define PAD_ROWS (NTOK*TOPK + NEXP*128)   // 34816

// ---------------- device scratch ----------------
__device__ int    g_counts[NEXP];
__device__ int    g_offsets[NEXP+1];
__device__ int    g_cursor[NEXP];
__device__ int    g_top2[NTOK*TOPK];
__device__ float  g_gates[NTOK*TOPK];
__device__ int    g_slot[NTOK*TOPK];
__device__ int    g_rowtok[PAD_ROWS];
__device__ __half g_inph[(size_t)NTOK*DDIM];       // inputs fp16 [N][D]
__device__ __half g_w1h[(size_t)NEXP*DDIM*HID];    // W1 fp16 [E][D][H]  (native layout)
__device__ __half g_w2h[(size_t)NEXP*HID*HID2];    // W2 fp16 [E][H][H2]
__device__ __half g_w3h[(size_t)NEXP*HID2*DDIM];   // W3 fp16 [E][H2][D]
__device__ __half g_h1h[(size_t)PAD_ROWS*HID];
__device__ __half g_h2h[(size_t)PAD_ROWS*HID2];
__device__ float  g_o3[(size_t)PAD_ROWS*DDIM];

// ---------------- helpers ----------------
__device__ __forceinline__ uint32_t smem_u32(const void* p){
    uint32_t a;
    asm("{ .reg .u64 t; cvta.to.shared.u64 t, %1; cvt.u32.u64 %0, t; }" : "=r"(a) : "l"(p));
    return a;
}
__device__ __forceinline__ void cp16(uint32_t dst, const void* src){
    asm volatile("cp.async.cg.shared.global [%0], [%1], 16;" :: "r"(dst), "l"(src) : "memory");
}
__device__ __forceinline__ void cp_commit(){ asm volatile("cp.async.commit_group;" ::: "memory"); }
template<int N> __device__ __forceinline__ void cp_wait(){
    asm volatile("cp.async.wait_group %0;" :: "n"(N) : "memory");
}
__device__ __forceinline__ void ldsm4(uint32_t& r0, uint32_t& r1, uint32_t& r2, uint32_t& r3, uint32_t addr){
    asm volatile("ldmatrix.sync.aligned.m8n8.x4.shared.b16 {%0,%1,%2,%3}, [%4];"
        : "=r"(r0), "=r"(r1), "=r"(r2), "=r"(r3) : "r"(addr));
}
__device__ __forceinline__ void ldsm4t(uint32_t& r0, uint32_t& r1, uint32_t& r2, uint32_t& r3, uint32_t addr){
    asm volatile("ldmatrix.sync.aligned.m8n8.x4.trans.shared.b16 {%0,%1,%2,%3}, [%4];"
        : "=r"(r0), "=r"(r1), "=r"(r2), "=r"(r3) : "r"(addr));
}
__device__ __forceinline__ void mma16816(float* c, uint32_t a0, uint32_t a1, uint32_t a2, uint32_t a3,
                                         uint32_t b0, uint32_t b1){
    asm volatile("mma.sync.aligned.m16n8k16.row.col.f32.f16.f16.f32 "
        "{%0,%1,%2,%3}, {%4,%5,%6,%7}, {%8,%9}, {%0,%1,%2,%3};"
        : "+f"(c[0]), "+f"(c[1]), "+f"(c[2]), "+f"(c[3])
        : "r"(a0), "r"(a1), "r"(a2), "r"(a3), "r"(b0), "r"(b1));
}

// ---------------- weight fp32->fp16 convert (native layout) + zero counts ----------------
#define W1_ELEMS ((size_t)NEXP*DDIM*HID)    // 8388608
#define W2_ELEMS ((size_t)NEXP*HID*HID2)    // 8388608
#define W3_ELEMS ((size_t)NEXP*HID2*DDIM)   // 4194304
#define WTOT4 ((W1_ELEMS + W2_ELEMS + W3_ELEMS) / 4)   // 5242880

__global__ void convw_kernel(const float* __restrict__ W1, const float* __restrict__ W2,
                             const float* __restrict__ W3){
    if (blockIdx.x == 0 && threadIdx.x < NEXP) g_counts[threadIdx.x] = 0;
    size_t i = ((size_t)blockIdx.x * blockDim.x + threadIdx.x) * 4;
    const float* src; __half* dst;
    if (i < W1_ELEMS)                 { src = W1 + i;                     dst = g_w1h + i; }
    else if (i < W1_ELEMS + W2_ELEMS) { src = W2 + (i - W1_ELEMS);        dst = g_w2h + (i - W1_ELEMS); }
    else                              { src = W3 + (i - W1_ELEMS - W2_ELEMS); dst = g_w3h + (i - W1_ELEMS - W2_ELEMS); }
    float4 v = *(const float4*)src;
    __half2 h0 = __floats2half2_rn(v.x, v.y);
    __half2 h1 = __floats2half2_rn(v.z, v.w);
    *(uint2*)dst = make_uint2(*(uint32_t*)&h0, *(uint32_t*)&h1);
}

// ---------------- fp16 mma.sync GEMM: C[M,Nout] = A @ W[e] + bias[e] ----------------
// A: [rows][K] fp16 (gathered for stage 1), B: [E][K][Nout] fp16 native layout.
// BM=128, BN=128, BK=32, 256 threads (8 warps as 2m x 4n), warp tile 64x32.
// A smem [m][k]: rows 32 halves padded to 40 (80B). B smem [k][n]: rows 128 halves padded to 136 (272B).
// B fragments via ldmatrix.x4.trans. 3-stage ring buffer, ONE __syncthreads per chunk.
#define LDA_H 40
#define LDB_H 136
#define B_REG_OFF 10240               // A region: 128*80
#define BUF_BYTES (10240 + 8704)      // + B region: 32*272 = 18944
#define STAGES 3
#define GSMEM_BYTES (STAGES * BUF_BYTES)   // 56832

template<bool GATHER, bool EXPERT, bool HALF_RELU_OUT>
__global__ void __launch_bounds__(256, 2)
gemm_mma(const __half* __restrict__ A, const __half* __restrict__ Bw,
         const float* __restrict__ bias, void* __restrict__ Cout,
         int K, int Nout)
{
    extern __shared__ __align__(16) char smem[];
    const uint32_t sb = smem_u32(smem);

    const int t = threadIdx.x, wid = t >> 5, l = t & 31;
    const int m0 = blockIdx.y * 128, n0 = blockIdx.x * 128;
    const int wm = wid >> 2, wn = wid & 3;          // 2 x 4 warps

    int e = 0;
    if (EXPERT) {
        #pragma unroll
        for (int i = 0; i < NEXP-1; i++) if (g_offsets[i+1] <= m0) e = i + 1;
    }
    const __half* Bb = Bw + (size_t)e * K * Nout;
    const float*  bb = bias + (size_t)e * Nout;

    // ---- A loader: 2 rows x 16B per thread (4 threads per row) ----
    const int ar0 = t >> 2, ar1 = 64 + (t >> 2), ach = t & 3;
    int tok0 = GATHER ? g_rowtok[m0 + ar0] : (m0 + ar0);
    int tok1 = GATHER ? g_rowtok[m0 + ar1] : (m0 + ar1);
    const __half* asrc0 = A + (size_t)tok0 * K + ach * 8;
    const __half* asrc1 = A + (size_t)tok1 * K + ach * 8;
    const uint32_t adst0 = ar0 * 80 + ach * 16;
    const uint32_t adst1 = ar1 * 80 + ach * 16;

    // ---- B loader: 2 k-rows x 16B per thread (16 threads per row) ----
    const int bk0 = t >> 4, bk1 = 16 + (t >> 4), bnc = t & 15;
    const __half* bsrc0 = Bb + (size_t)bk0 * Nout + n0 + bnc * 8;
    const __half* bsrc1 = Bb + (size_t)bk1 * Nout + n0 + bnc * 8;
    const uint32_t bdst0 = B_REG_OFF + bk0 * 272 + bnc * 16;
    const uint32_t bdst1 = B_REG_OFF + bk1 * 272 + bnc * 16;

    // ---- ldmatrix lane addressing (byte offsets within a buffer) ----
    uint32_t a_off[4], b_off[2];
    {
        int a_lrow = l & 15, a_lcol = (l >> 4) * 8;
        #pragma unroll
        for (int mt = 0; mt < 4; mt++)
            a_off[mt] = ((wm*64 + mt*16 + a_lrow) * LDA_H + a_lcol) * 2;
        int b_krow = l & 15, b_ncol = (l >> 4) * 8;
        #pragma unroll
        for (int p = 0; p < 2; p++)
            b_off[p] = B_REG_OFF + (b_krow * LDB_H + wn*32 + p*16 + b_ncol) * 2;
    }

    float acc[4][4][4];
    #pragma unroll
    for (int i = 0; i < 4; i++)
        #pragma unroll
        for (int j = 0; j < 4; j++)
            #pragma unroll
            for (int r = 0; r < 4; r++) acc[i][j][r] = 0.f;

    const int C = K >> 5;   // >= 16 always; STAGES-1 preloads safe

    auto load_tile = [&](int c){
        const int kb = c * 32;
        const uint32_t base = sb + (uint32_t)(c % STAGES) * BUF_BYTES;
        cp16(base + adst0, asrc0 + kb);
        cp16(base + adst1, asrc1 + kb);
        cp16(base + bdst0, bsrc0 + (size_t)kb * Nout);
        cp16(base + bdst1, bsrc1 + (size_t)kb * Nout);
        cp_commit();
    };

    load_tile(0);
    load_tile(1);

    for (int c = 0; c < C; c++) {
        // tile c is complete when at most 1 newer group is pending; drain fully on last iter
        if (c + 1 < C) cp_wait<1>();
        else           cp_wait<0>();
        __syncthreads();   // single barrier: all threads see tile c; with 3 buffers the
                           // prefetch below writes the buffer last read at tile c-1 (pre-barrier)
        if (c + 2 < C) load_tile(c + 2);

        const uint32_t base = sb + (uint32_t)(c % STAGES) * BUF_BYTES;
        #pragma unroll
        for (int ks = 0; ks < 2; ks++) {
            uint32_t a[4][4], b[2][4];
            #pragma unroll
            for (int mt = 0; mt < 4; mt++)
                ldsm4(a[mt][0], a[mt][1], a[mt][2], a[mt][3], base + a_off[mt] + ks*32);
            #pragma unroll
            for (int p = 0; p < 2; p++)
                ldsm4t(b[p][0], b[p][1], b[p][2], b[p][3], base + b_off[p] + ks*16*LDB_H*2);
            #pragma unroll
            for (int mt = 0; mt < 4; mt++)
                #pragma unroll
                for (int nt = 0; nt < 4; nt++)
                    mma16816(acc[mt][nt], a[mt][0], a[mt][1], a[mt][2], a[mt][3],
                             b[nt>>1][(nt&1)*2], b[nt>>1][(nt&1)*2+1]);
        }
    }

    // ---- epilogue ----
    const int grp = l >> 2, tig = l & 3;
    #pragma unroll
    for (int mt = 0; mt < 4; mt++) {
        const int row = m0 + wm*64 + mt*16 + grp;
        #pragma unroll
        for (int nt = 0; nt < 4; nt++) {
            const int col = n0 + wn*32 + nt*8 + tig*2;
            float bv0 = bb[col], bv1 = bb[col+1];
            float v0 = acc[mt][nt][0] + bv0, v1 = acc[mt][nt][1] + bv1;
            float v2 = acc[mt][nt][2] + bv0, v3 = acc[mt][nt][3] + bv1;
            if (HALF_RELU_OUT) {
                v0 = fmaxf(v0, 0.f); v1 = fmaxf(v1, 0.f);
                v2 = fmaxf(v2, 0.f); v3 = fmaxf(v3, 0.f);
                __half2 h0 = __floats2half2_rn(v0, v1);
                __half2 h1 = __floats2half2_rn(v2, v3);
                *(uint32_t*)((__half*)Cout + (size_t)row     * Nout + col) = *(uint32_t*)&h0;
                *(uint32_t*)((__half*)Cout + (size_t)(row+8) * Nout + col) = *(uint32_t*)&h1;
            } else {
                *(float2*)((float*)Cout + (size_t)row     * Nout + col) = make_float2(v0, v1);
                *(float2*)((float*)Cout + (size_t)(row+8) * Nout + col) = make_float2(v2, v3);
            }
        }
    }
}

// ---------------- router SIMT fp32 GEMM (exact; feeds top-k), BM=64 + fp16 input emit ----------------
__global__ void __launch_bounds__(256, 2)
router_gemm64(const float* __restrict__ A, const float* __restrict__ W,
              const float* __restrict__ bias, float* __restrict__ C)
{
    const int m0 = blockIdx.x * 64;

    __shared__ float As[16][64];
    __shared__ float Bs[16][128];

    const int t  = threadIdx.x;
    const int tx = t & 15;       // col group (8 cols)
    const int ty = t >> 4;       // row group (4 rows)

    const int am = t >> 2, aj = t & 3;
    const int arowi = m0 + am;
    const float* arow = A + (size_t)arowi * DDIM + aj * 4;
    __half* hdst = g_inph + (size_t)arowi * DDIM + aj * 4;

    const int bk = t >> 5;
    const int bn = (t & 31) * 4;
    const float* brow0 = W + (size_t)bk       * EMBD + bn;
    const float* brow1 = W + (size_t)(bk + 8) * EMBD + bn;

    float acc[4][8];
    #pragma unroll
    for (int i = 0; i < 4; i++)
        #pragma unroll
        for (int j = 0; j < 8; j++) acc[i][j] = 0.f;

    for (int kb = 0; kb < DDIM; kb += 16) {
        float4 a0 = *(const float4*)(arow + kb);
        float4 b0 = *(const float4*)(brow0 + (size_t)kb * EMBD);
        float4 b1 = *(const float4*)(brow1 + (size_t)kb * EMBD);

        {
            __half2 h0 = __floats2half2_rn(a0.x, a0.y);
            __half2 h1 = __floats2half2_rn(a0.z, a0.w);
            *(uint2*)(hdst + kb) = make_uint2(*(uint32_t*)&h0, *(uint32_t*)&h1);
        }

        As[aj*4+0][am] = a0.x; As[aj*4+1][am] = a0.y;
        As[aj*4+2][am] = a0.z; As[aj*4+3][am] = a0.w;
        *(float4*)&Bs[bk][bn]   = b0;
        *(float4*)&Bs[bk+8][bn] = b1;
        __syncthreads();

        #pragma unroll
        for (int k = 0; k < 16; k++) {
            float4 av  = *(const float4*)&As[k][ty*4];
            float4 bv0 = *(const float4*)&Bs[k][tx*8];
            float4 bv1 = *(const float4*)&Bs[k][tx*8+4];
            float a[4] = {av.x, av.y, av.z, av.w};
            float b[8] = {bv0.x, bv0.y, bv0.z, bv0.w, bv1.x, bv1.y, bv1.z, bv1.w};
            #pragma unroll
            for (int i = 0; i < 4; i++)
                #pragma unroll
                for (int j = 0; j < 8; j++)
                    acc[i][j] = fmaf(a[i], b[j], acc[i][j]);
        }
        __syncthreads();
    }

    #pragma unroll
    for (int i = 0; i < 4; i++) {
        float* crow = C + (size_t)(m0 + ty*4 + i) * EMBD + tx*8;
        float4 v0, v1;
        v0.x = acc[i][0] + bias[tx*8+0]; v0.y = acc[i][1] + bias[tx*8+1];
        v0.z = acc[i][2] + bias[tx*8+2]; v0.w = acc[i][3] + bias[tx*8+3];
        v1.x = acc[i][4] + bias[tx*8+4]; v1.y = acc[i][5] + bias[tx*8+5];
        v1.z = acc[i][6] + bias[tx*8+6]; v1.w = acc[i][7] + bias[tx*8+7];
        *(float4*)crow       = v0;
        *(float4*)(crow + 4) = v1;
    }
}

// ---------------- gating / scatter / combine ----------------
__global__ void gating_kernel(const float* __restrict__ q,
                              const float* __restrict__ emb,
                              float* __restrict__ probs_out)
{
    int gw   = (blockIdx.x * blockDim.x + threadIdx.x) >> 5;
    int lane = threadIdx.x & 31;
    if (gw >= NTOK) return;

    const float* qr = q + (size_t)gw * EMBD;
    float qv[4];
    #pragma unroll
    for (int u = 0; u < 4; u++) qv[u] = qr[lane + 32*u];

    float sc[NEXP];
    #pragma unroll
    for (int e = 0; e < NEXP; e++) {
        float d = 0.f;
        #pragma unroll
        for (int u = 0; u < 4; u++) {
            float diff = qv[u] - emb[e*EMBD + lane + 32*u];
            d = fmaf(diff, diff, d);
        }
        #pragma unroll
        for (int o = 16; o > 0; o >>= 1) d += __shfl_xor_sync(0xffffffffu, d, o);
        sc[e] = -d;
    }

    float mx = sc[0];
    #pragma unroll
    for (int e = 1; e < NEXP; e++) mx = fmaxf(mx, sc[e]);
    float ex[NEXP]; float sum = 0.f;
    #pragma unroll
    for (int e = 0; e < NEXP; e++) { ex[e] = expf(sc[e] - mx); sum += ex[e]; }
    float inv = 1.f / sum;
    #pragma unroll
    for (int e = 0; e < NEXP; e++)
        if (lane == e) probs_out[(size_t)gw*NEXP + e] = ex[e] * inv;

    int i0 = 0; float v0 = sc[0];
    #pragma unroll
    for (int e = 1; e < NEXP; e++) if (sc[e] > v0) { v0 = sc[e]; i0 = e; }
    int i1 = -1; float v1 = -INFINITY;
    #pragma unroll
    for (int e = 0; e < NEXP; e++) if (e != i0 && sc[e] > v1) { v1 = sc[e]; i1 = e; }

    if (lane == 0) {
        float e1 = expf(v1 - v0);
        float s  = 1.f + e1;
        g_top2[gw*2]    = i0; g_top2[gw*2+1]  = i1;
        g_gates[gw*2]   = 1.f / s; g_gates[gw*2+1] = e1 / s;
        atomicAdd(&g_counts[i0], 1);
        atomicAdd(&g_counts[i1], 1);
    }
}

__global__ void offsets_kernel() {
    if (threadIdx.x == 0) {
        int off = 0;
        for (int e = 0; e < NEXP; e++) {
            g_offsets[e] = off;
            g_cursor[e]  = off;
            off += (g_counts[e] + 127) & ~127;
        }
        g_offsets[NEXP] = off;
    }
}

__global__ void scatter_kernel() {
    int i = blockIdx.x * blockDim.x + threadIdx.x;
    if (i < NTOK*TOPK) {
        int e   = g_top2[i];
        int pos = atomicAdd(&g_cursor[e], 1);
        g_rowtok[pos] = i >> 1;
        g_slot[i]     = pos;
    }
}

__global__ void combine_kernel(float* __restrict__ out)
{
    int n = blockIdx.x;
    int t = threadIdx.x;
    int s0 = g_slot[2*n], s1 = g_slot[2*n+1];
    float g0 = g_gates[2*n], g1 = g_gates[2*n+1];
    const float4* r0 = (const float4*)(g_o3 + (size_t)s0 * DDIM);
    const float4* r1 = (const float4*)(g_o3 + (size_t)s1 * DDIM);
    float4 a = r0[t], b = r1[t];
    float4 v;
    v.x = g0*a.x + g1*b.x; v.y = g0*a.y + g1*b.y;
    v.z = g0*a.z + g1*b.z; v.w = g0*a.w + g1*b.w;
    ((float4*)(out + (size_t)n * DDIM))[t] = v;
}

// ---------------- launch ----------------
extern "C" void kernel_launch(void* const* d_in, const int* in_sizes, int n_in,
                              void* d_out, int out_size)
{
    const float* inputs    = (const float*)d_in[0];
    const float* router_W  = (const float*)d_in[1];
    const float* router_b  = (const float*)d_in[2];
    const float* expert_emb= (const float*)d_in[3];
    const float* W1 = (const float*)d_in[4];
    const float* b1 = (const float*)d_in[5];
    const float* W2 = (const float*)d_in[6];
    const float* b2 = (const float*)d_in[7];
    const float* W3 = (const float*)d_in[8];
    const float* b3 = (const float*)d_in[9];

    float* out       = (float*)d_out;
    float* out_comb  = out;
    float* out_q     = out + (size_t)NTOK * DDIM;
    float* out_probs = out + (size_t)NTOK * DDIM + (size_t)NTOK * EMBD;

    __half *inph, *w1h, *w2h, *w3h, *h1h, *h2h;
    float *o3p;
    cudaGetSymbolAddress((void**)&inph, g_inph);
    cudaGetSymbolAddress((void**)&w1h,  g_w1h);
    cudaGetSymbolAddress((void**)&w2h,  g_w2h);
    cudaGetSymbolAddress((void**)&w3h,  g_w3h);
    cudaGetSymbolAddress((void**)&h1h,  g_h1h);
    cudaGetSymbolAddress((void**)&h2h,  g_h2h);
    cudaGetSymbolAddress((void**)&o3p,  g_o3);

    cudaFuncSetAttribute(gemm_mma<true,true,true>,   cudaFuncAttributeMaxDynamicSharedMemorySize, GSMEM_BYTES);
    cudaFuncSetAttribute(gemm_mma<false,true,true>,  cudaFuncAttributeMaxDynamicSharedMemorySize, GSMEM_BYTES);
    cudaFuncSetAttribute(gemm_mma<false,true,false>, cudaFuncAttributeMaxDynamicSharedMemorySize, GSMEM_BYTES);

    // launch 0: weight convert (+ zero counts)
    convw_kernel<<<(unsigned)(WTOT4/256), 256>>>(W1, W2, W3);
    // launch 1: router fp32 (exact; also emits fp16 inputs)
    router_gemm64<<<NTOK/64, 256>>>(inputs, router_W, router_b, out_q);
    // launch 2-4: gating, offsets, scatter
    gating_kernel<<<(NTOK*32)/256, 256>>>(out_q, expert_emb, out_probs);
    offsets_kernel<<<1, 32>>>();
    scatter_kernel<<<(NTOK*TOPK + 255)/256, 256>>>();

    // launch 5-7: expert MLP on tensor cores (fp16 mma.sync, BK=32, 3-stage ring, 1 sync/chunk)
    gemm_mma<true,true,true><<<dim3(HID/128,  PAD_ROWS/128), 256, GSMEM_BYTES>>>(
        inph, w1h, b1, h1h, DDIM, HID);
    gemm_mma<false,true,true><<<dim3(HID2/128, PAD_ROWS/128), 256, GSMEM_BYTES>>>(
        h1h, w2h, b2, h2h, HID, HID2);
    gemm_mma<false,true,false><<<dim3(DDIM/128, PAD_ROWS/128), 256, GSMEM_BYTES>>>(
        h2h, w3h, b3, o3p, HID2, DDIM);

    combine_kernel<<<NTOK, 128>>>(out_comb);
}

// round 12
// speedup vs baseline: 1.3052x; 1.0066x over previous
#include <cuda_runtime.h>
#include <cuda_fp16.h>
#include <math.h>
#include <cstdint>

#define NTOK 16384
#define DDIM 512
#define NEXP 16
#define TOPK 2
#define EMBD 128
#define HID  1024
#define HID2 512
#define PAD_ROWS (NTOK*TOPK + NEXP*128)   // 34816

// ---------------- device scratch ----------------
__device__ int    g_counts[NEXP];
__device__ int    g_offsets[NEXP+1];
__device__ int    g_cursor[NEXP];
__device__ int    g_top2[NTOK*TOPK];
__device__ float  g_gates[NTOK*TOPK];
__device__ int    g_slot[NTOK*TOPK];
__device__ int    g_rowtok[PAD_ROWS];
__device__ __half g_inph[(size_t)NTOK*DDIM];       // inputs fp16 [N][D]
__device__ __half g_w1h[(size_t)NEXP*DDIM*HID];    // W1 fp16 [E][D][H]  (native layout)
__device__ __half g_w2h[(size_t)NEXP*HID*HID2];    // W2 fp16 [E][H][H2]
__device__ __half g_w3h[(size_t)NEXP*HID2*DDIM];   // W3 fp16 [E][H2][D]
__device__ __half g_h1h[(size_t)PAD_ROWS*HID];
__device__ __half g_h2h[(size_t)PAD_ROWS*HID2];
__device__ __half g_o3h[(size_t)PAD_ROWS*DDIM];    // stage-3 output fp16

// ---------------- helpers ----------------
__device__ __forceinline__ uint32_t smem_u32(const void* p){
    uint32_t a;
    asm("{ .reg .u64 t; cvta.to.shared.u64 t, %1; cvt.u32.u64 %0, t; }" : "=r"(a) : "l"(p));
    return a;
}
__device__ __forceinline__ void cp16(uint32_t dst, const void* src){
    asm volatile("cp.async.cg.shared.global [%0], [%1], 16;" :: "r"(dst), "l"(src) : "memory");
}
__device__ __forceinline__ void cp_commit(){ asm volatile("cp.async.commit_group;" ::: "memory"); }
template<int N> __device__ __forceinline__ void cp_wait(){
    asm volatile("cp.async.wait_group %0;" :: "n"(N) : "memory");
}
__device__ __forceinline__ void ldsm4(uint32_t& r0, uint32_t& r1, uint32_t& r2, uint32_t& r3, uint32_t addr){
    asm volatile("ldmatrix.sync.aligned.m8n8.x4.shared.b16 {%0,%1,%2,%3}, [%4];"
        : "=r"(r0), "=r"(r1), "=r"(r2), "=r"(r3) : "r"(addr));
}
__device__ __forceinline__ void ldsm4t(uint32_t& r0, uint32_t& r1, uint32_t& r2, uint32_t& r3, uint32_t addr){
    asm volatile("ldmatrix.sync.aligned.m8n8.x4.trans.shared.b16 {%0,%1,%2,%3}, [%4];"
        : "=r"(r0), "=r"(r1), "=r"(r2), "=r"(r3) : "r"(addr));
}
__device__ __forceinline__ void mma16816(float* c, uint32_t a0, uint32_t a1, uint32_t a2, uint32_t a3,
                                         uint32_t b0, uint32_t b1){
    asm volatile("mma.sync.aligned.m16n8k16.row.col.f32.f16.f16.f32 "
        "{%0,%1,%2,%3}, {%4,%5,%6,%7}, {%8,%9}, {%0,%1,%2,%3};"
        : "+f"(c[0]), "+f"(c[1]), "+f"(c[2]), "+f"(c[3])
        : "r"(a0), "r"(a1), "r"(a2), "r"(a3), "r"(b0), "r"(b1));
}

// ---------------- weight fp32->fp16 convert (native layout) + zero counts ----------------
#define W1_ELEMS ((size_t)NEXP*DDIM*HID)    // 8388608
#define W2_ELEMS ((size_t)NEXP*HID*HID2)    // 8388608
#define W3_ELEMS ((size_t)NEXP*HID2*DDIM)   // 4194304
#define WTOT4 ((W1_ELEMS + W2_ELEMS + W3_ELEMS) / 4)   // 5242880

__global__ void convw_kernel(const float* __restrict__ W1, const float* __restrict__ W2,
                             const float* __restrict__ W3){
    if (blockIdx.x == 0 && threadIdx.x < NEXP) g_counts[threadIdx.x] = 0;
    size_t i = ((size_t)blockIdx.x * blockDim.x + threadIdx.x) * 4;
    const float* src; __half* dst;
    if (i < W1_ELEMS)                 { src = W1 + i;                     dst = g_w1h + i; }
    else if (i < W1_ELEMS + W2_ELEMS) { src = W2 + (i - W1_ELEMS);        dst = g_w2h + (i - W1_ELEMS); }
    else                              { src = W3 + (i - W1_ELEMS - W2_ELEMS); dst = g_w3h + (i - W1_ELEMS - W2_ELEMS); }
    float4 v = *(const float4*)src;
    __half2 h0 = __floats2half2_rn(v.x, v.y);
    __half2 h1 = __floats2half2_rn(v.z, v.w);
    *(uint2*)dst = make_uint2(*(uint32_t*)&h0, *(uint32_t*)&h1);
}

// ---------------- fp16 mma.sync GEMM: C[M,Nout] = A @ W[e] + bias[e] ----------------
// BM=128, BN=128, BK=32, 256 threads (8 warps as 2m x 4n), warp tile 64x32.
// 3-stage cp.async ring, ONE __syncthreads per chunk (proven R10 winner).
#define LDA_H 40
#define LDB_H 136
#define B_REG_OFF 10240               // A region: 128*80
#define BUF_BYTES (10240 + 8704)      // + B region: 32*272 = 18944
#define STAGES 3
#define GSMEM_BYTES (STAGES * BUF_BYTES)   // 56832

template<bool GATHER, bool EXPERT, bool RELU, bool OUT_HALF>
__global__ void __launch_bounds__(256, 2)
gemm_mma(const __half* __restrict__ A, const __half* __restrict__ Bw,
         const float* __restrict__ bias, void* __restrict__ Cout,
         int K, int Nout)
{
    extern __shared__ __align__(16) char smem[];
    const uint32_t sb = smem_u32(smem);

    const int t = threadIdx.x, wid = t >> 5, l = t & 31;
    const int m0 = blockIdx.y * 128, n0 = blockIdx.x * 128;
    const int wm = wid >> 2, wn = wid & 3;          // 2 x 4 warps

    int e = 0;
    if (EXPERT) {
        #pragma unroll
        for (int i = 0; i < NEXP-1; i++) if (g_offsets[i+1] <= m0) e = i + 1;
    }
    const __half* Bb = Bw + (size_t)e * K * Nout;
    const float*  bb = bias + (size_t)e * Nout;

    // ---- A loader: 2 rows x 16B per thread (4 threads per row) ----
    const int ar0 = t >> 2, ar1 = 64 + (t >> 2), ach = t & 3;
    int tok0 = GATHER ? g_rowtok[m0 + ar0] : (m0 + ar0);
    int tok1 = GATHER ? g_rowtok[m0 + ar1] : (m0 + ar1);
    const __half* asrc0 = A + (size_t)tok0 * K + ach * 8;
    const __half* asrc1 = A + (size_t)tok1 * K + ach * 8;
    const uint32_t adst0 = ar0 * 80 + ach * 16;
    const uint32_t adst1 = ar1 * 80 + ach * 16;

    // ---- B loader: 2 k-rows x 16B per thread (16 threads per row) ----
    const int bk0 = t >> 4, bk1 = 16 + (t >> 4), bnc = t & 15;
    const __half* bsrc0 = Bb + (size_t)bk0 * Nout + n0 + bnc * 8;
    const __half* bsrc1 = Bb + (size_t)bk1 * Nout + n0 + bnc * 8;
    const uint32_t bdst0 = B_REG_OFF + bk0 * 272 + bnc * 16;
    const uint32_t bdst1 = B_REG_OFF + bk1 * 272 + bnc * 16;

    // ---- ldmatrix lane addressing (byte offsets within a buffer) ----
    uint32_t a_off[4], b_off[2];
    {
        int a_lrow = l & 15, a_lcol = (l >> 4) * 8;
        #pragma unroll
        for (int mt = 0; mt < 4; mt++)
            a_off[mt] = ((wm*64 + mt*16 + a_lrow) * LDA_H + a_lcol) * 2;
        int b_krow = l & 15, b_ncol = (l >> 4) * 8;
        #pragma unroll
        for (int p = 0; p < 2; p++)
            b_off[p] = B_REG_OFF + (b_krow * LDB_H + wn*32 + p*16 + b_ncol) * 2;
    }

    float acc[4][4][4];
    #pragma unroll
    for (int i = 0; i < 4; i++)
        #pragma unroll
        for (int j = 0; j < 4; j++)
            #pragma unroll
            for (int r = 0; r < 4; r++) acc[i][j][r] = 0.f;

    const int C = K >> 5;

    auto load_tile = [&](int c){
        const int kb = c * 32;
        const uint32_t base = sb + (uint32_t)(c % STAGES) * BUF_BYTES;
        cp16(base + adst0, asrc0 + kb);
        cp16(base + adst1, asrc1 + kb);
        cp16(base + bdst0, bsrc0 + (size_t)kb * Nout);
        cp16(base + bdst1, bsrc1 + (size_t)kb * Nout);
        cp_commit();
    };

    load_tile(0);
    load_tile(1);

    for (int c = 0; c < C; c++) {
        if (c + 1 < C) cp_wait<1>();
        else           cp_wait<0>();
        __syncthreads();   // single barrier: with 3 buffers the prefetch below writes
                           // the buffer last read at tile c-1 (pre-barrier)
        if (c + 2 < C) load_tile(c + 2);

        const uint32_t base = sb + (uint32_t)(c % STAGES) * BUF_BYTES;
        #pragma unroll
        for (int ks = 0; ks < 2; ks++) {
            uint32_t a[4][4], b[2][4];
            #pragma unroll
            for (int mt = 0; mt < 4; mt++)
                ldsm4(a[mt][0], a[mt][1], a[mt][2], a[mt][3], base + a_off[mt] + ks*32);
            #pragma unroll
            for (int p = 0; p < 2; p++)
                ldsm4t(b[p][0], b[p][1], b[p][2], b[p][3], base + b_off[p] + ks*16*LDB_H*2);
            #pragma unroll
            for (int mt = 0; mt < 4; mt++)
                #pragma unroll
                for (int nt = 0; nt < 4; nt++)
                    mma16816(acc[mt][nt], a[mt][0], a[mt][1], a[mt][2], a[mt][3],
                             b[nt>>1][(nt&1)*2], b[nt>>1][(nt&1)*2+1]);
        }
    }

    // ---- epilogue ----
    const int grp = l >> 2, tig = l & 3;
    #pragma unroll
    for (int mt = 0; mt < 4; mt++) {
        const int row = m0 + wm*64 + mt*16 + grp;
        #pragma unroll
        for (int nt = 0; nt < 4; nt++) {
            const int col = n0 + wn*32 + nt*8 + tig*2;
            float bv0 = bb[col], bv1 = bb[col+1];
            float v0 = acc[mt][nt][0] + bv0, v1 = acc[mt][nt][1] + bv1;
            float v2 = acc[mt][nt][2] + bv0, v3 = acc[mt][nt][3] + bv1;
            if (RELU) {
                v0 = fmaxf(v0, 0.f); v1 = fmaxf(v1, 0.f);
                v2 = fmaxf(v2, 0.f); v3 = fmaxf(v3, 0.f);
            }
            if (OUT_HALF) {
                __half2 h0 = __floats2half2_rn(v0, v1);
                __half2 h1 = __floats2half2_rn(v2, v3);
                *(uint32_t*)((__half*)Cout + (size_t)row     * Nout + col) = *(uint32_t*)&h0;
                *(uint32_t*)((__half*)Cout + (size_t)(row+8) * Nout + col) = *(uint32_t*)&h1;
            } else {
                *(float2*)((float*)Cout + (size_t)row     * Nout + col) = make_float2(v0, v1);
                *(float2*)((float*)Cout + (size_t)(row+8) * Nout + col) = make_float2(v2, v3);
            }
        }
    }
}

// ---------------- router fp32 GEMM + FUSED gating (exact fp32 top-k path) ----------------
// BM=64, BN=128(=EMBD), K=512. Emits fp16 inputs, q (fp32), probs, top2/gates/counts.
__global__ void __launch_bounds__(256, 2)
router_gate_kernel(const float* __restrict__ A, const float* __restrict__ W,
                   const float* __restrict__ bias, float* __restrict__ C,
                   const float* __restrict__ emb, float* __restrict__ probs_out)
{
    const int m0 = blockIdx.x * 64;

    __shared__ float As[16][64];
    __shared__ float Bs[16][128];
    __shared__ float Es[NEXP][EMBD];   // expert embeddings

    const int t  = threadIdx.x;
    const int tx = t & 15;       // col group (8 cols)
    const int ty = t >> 4;       // row group (4 rows)

    // stage expert embeddings (2048 floats, 8 per thread); consumed after first __syncthreads
    #pragma unroll
    for (int u = 0; u < 8; u++) {
        int idx = t + u * 256;
        Es[idx >> 7][idx & 127] = emb[idx];
    }

    const int am = t >> 2, aj = t & 3;
    const int arowi = m0 + am;
    const float* arow = A + (size_t)arowi * DDIM + aj * 4;
    __half* hdst = g_inph + (size_t)arowi * DDIM + aj * 4;

    const int bk = t >> 5;
    const int bn = (t & 31) * 4;
    const float* brow0 = W + (size_t)bk       * EMBD + bn;
    const float* brow1 = W + (size_t)(bk + 8) * EMBD + bn;

    float acc[4][8];
    #pragma unroll
    for (int i = 0; i < 4; i++)
        #pragma unroll
        for (int j = 0; j < 8; j++) acc[i][j] = 0.f;

    for (int kb = 0; kb < DDIM; kb += 16) {
        float4 a0 = *(const float4*)(arow + kb);
        float4 b0 = *(const float4*)(brow0 + (size_t)kb * EMBD);
        float4 b1 = *(const float4*)(brow1 + (size_t)kb * EMBD);

        {   // emit fp16 inputs (each element written exactly once across the grid)
            __half2 h0 = __floats2half2_rn(a0.x, a0.y);
            __half2 h1 = __floats2half2_rn(a0.z, a0.w);
            *(uint2*)(hdst + kb) = make_uint2(*(uint32_t*)&h0, *(uint32_t*)&h1);
        }

        As[aj*4+0][am] = a0.x; As[aj*4+1][am] = a0.y;
        As[aj*4+2][am] = a0.z; As[aj*4+3][am] = a0.w;
        *(float4*)&Bs[bk][bn]   = b0;
        *(float4*)&Bs[bk+8][bn] = b1;
        __syncthreads();

        #pragma unroll
        for (int k = 0; k < 16; k++) {
            float4 av  = *(const float4*)&As[k][ty*4];
            float4 bv0 = *(const float4*)&Bs[k][tx*8];
            float4 bv1 = *(const float4*)&Bs[k][tx*8+4];
            float a[4] = {av.x, av.y, av.z, av.w};
            float b[8] = {bv0.x, bv0.y, bv0.z, bv0.w, bv1.x, bv1.y, bv1.z, bv1.w};
            #pragma unroll
            for (int i = 0; i < 4; i++)
                #pragma unroll
                for (int j = 0; j < 8; j++)
                    acc[i][j] = fmaf(a[i], b[j], acc[i][j]);
        }
        __syncthreads();
    }

    // ---- epilogue: write q, then fused gating ----
    #pragma unroll 1
    for (int i = 0; i < 4; i++) {
        const int r = m0 + ty*4 + i;
        float qv[8];
        #pragma unroll
        for (int j = 0; j < 8; j++) qv[j] = acc[i][j] + bias[tx*8 + j];

        {   // write q row segment
            float* crow = C + (size_t)r * EMBD + tx*8;
            *(float4*)crow       = make_float4(qv[0], qv[1], qv[2], qv[3]);
            *(float4*)(crow + 4) = make_float4(qv[4], qv[5], qv[6], qv[7]);
        }

        // distances: each of 16 lanes (same ty) holds 8 contiguous cols
        float sc[NEXP];
        #pragma unroll
        for (int e = 0; e < NEXP; e++) {
            float d = 0.f;
            #pragma unroll
            for (int j = 0; j < 8; j++) {
                float diff = qv[j] - Es[e][tx*8 + j];
                d = fmaf(diff, diff, d);
            }
            #pragma unroll
            for (int o = 8; o > 0; o >>= 1) d += __shfl_xor_sync(0xffffffffu, d, o);
            sc[e] = -d;   // identical across the 16-lane group
        }

        float mx = sc[0];
        #pragma unroll
        for (int e = 1; e < NEXP; e++) mx = fmaxf(mx, sc[e]);
        float ex[NEXP]; float sum = 0.f;
        #pragma unroll
        for (int e = 0; e < NEXP; e++) { ex[e] = expf(sc[e] - mx); sum += ex[e]; }
        float inv = 1.f / sum;
        probs_out[(size_t)r * NEXP + tx] = ex[tx] * inv;   // lane tx writes expert tx

        if (tx == 0) {
            int i0 = 0; float v0 = sc[0];
            #pragma unroll
            for (int e = 1; e < NEXP; e++) if (sc[e] > v0) { v0 = sc[e]; i0 = e; }
            int i1 = -1; float v1 = -INFINITY;
            #pragma unroll
            for (int e = 0; e < NEXP; e++) if (e != i0 && sc[e] > v1) { v1 = sc[e]; i1 = e; }
            float e1 = expf(v1 - v0);
            float s  = 1.f + e1;
            g_top2[r*2]   = i0;      g_top2[r*2+1]  = i1;
            g_gates[r*2]  = 1.f / s; g_gates[r*2+1] = e1 / s;
            atomicAdd(&g_counts[i0], 1);
            atomicAdd(&g_counts[i1], 1);
        }
    }
}

// ---------------- offsets / scatter / combine ----------------
__global__ void offsets_kernel() {
    if (threadIdx.x == 0) {
        int off = 0;
        for (int e = 0; e < NEXP; e++) {
            g_offsets[e] = off;
            g_cursor[e]  = off;
            off += (g_counts[e] + 127) & ~127;
        }
        g_offsets[NEXP] = off;
    }
}

__global__ void scatter_kernel() {
    int i = blockIdx.x * blockDim.x + threadIdx.x;
    if (i < NTOK*TOPK) {
        int e   = g_top2[i];
        int pos = atomicAdd(&g_cursor[e], 1);
        g_rowtok[pos] = i >> 1;
        g_slot[i]     = pos;
    }
}

__global__ void combine_kernel(float* __restrict__ out)
{
    int n = blockIdx.x;
    int t = threadIdx.x;   // 128 threads, 4 outputs each over D=512
    int s0 = g_slot[2*n], s1 = g_slot[2*n+1];
    float g0 = g_gates[2*n], g1 = g_gates[2*n+1];
    const __half2* r0 = (const __half2*)(g_o3h + (size_t)s0 * DDIM);
    const __half2* r1 = (const __half2*)(g_o3h + (size_t)s1 * DDIM);
    float2 a0 = __half22float2(r0[2*t]),   a1 = __half22float2(r0[2*t+1]);
    float2 b0 = __half22float2(r1[2*t]),   b1 = __half22float2(r1[2*t+1]);
    float4 v;
    v.x = g0*a0.x + g1*b0.x; v.y = g0*a0.y + g1*b0.y;
    v.z = g0*a1.x + g1*b1.x; v.w = g0*a1.y + g1*b1.y;
    ((float4*)(out + (size_t)n * DDIM))[t] = v;
}

// ---------------- launch ----------------
extern "C" void kernel_launch(void* const* d_in, const int* in_sizes, int n_in,
                              void* d_out, int out_size)
{
    const float* inputs    = (const float*)d_in[0];
    const float* router_W  = (const float*)d_in[1];
    const float* router_b  = (const float*)d_in[2];
    const float* expert_emb= (const float*)d_in[3];
    const float* W1 = (const float*)d_in[4];
    const float* b1 = (const float*)d_in[5];
    const float* W2 = (const float*)d_in[6];
    const float* b2 = (const float*)d_in[7];
    const float* W3 = (const float*)d_in[8];
    const float* b3 = (const float*)d_in[9];

    float* out       = (float*)d_out;
    float* out_comb  = out;
    float* out_q     = out + (size_t)NTOK * DDIM;
    float* out_probs = out + (size_t)NTOK * DDIM + (size_t)NTOK * EMBD;

    __half *inph, *w1h, *w2h, *w3h, *h1h, *h2h, *o3h;
    cudaGetSymbolAddress((void**)&inph, g_inph);
    cudaGetSymbolAddress((void**)&w1h,  g_w1h);
    cudaGetSymbolAddress((void**)&w2h,  g_w2h);
    cudaGetSymbolAddress((void**)&w3h,  g_w3h);
    cudaGetSymbolAddress((void**)&h1h,  g_h1h);
    cudaGetSymbolAddress((void**)&h2h,  g_h2h);
    cudaGetSymbolAddress((void**)&o3h,  g_o3h);

    cudaFuncSetAttribute(gemm_mma<true,true,true,true>,    cudaFuncAttributeMaxDynamicSharedMemorySize, GSMEM_BYTES);
    cudaFuncSetAttribute(gemm_mma<false,true,true,true>,   cudaFuncAttributeMaxDynamicSharedMemorySize, GSMEM_BYTES);
    cudaFuncSetAttribute(gemm_mma<false,true,false,true>,  cudaFuncAttributeMaxDynamicSharedMemorySize, GSMEM_BYTES);

    // launch 0: weight convert (+ zero counts)
    convw_kernel<<<(unsigned)(WTOT4/256), 256>>>(W1, W2, W3);
    // launch 1: router fp32 + fused gating (exact; also emits fp16 inputs)
    router_gate_kernel<<<NTOK/64, 256>>>(inputs, router_W, router_b, out_q,
                                         expert_emb, out_probs);
    // launch 2-3: offsets, scatter
    offsets_kernel<<<1, 32>>>();
    scatter_kernel<<<(NTOK*TOPK + 255)/256, 256>>>();

    // launch 4-6: expert MLP on tensor cores (fp16 mma.sync, BK=32, 3-stage ring)
    gemm_mma<true,true,true,true><<<dim3(HID/128,  PAD_ROWS/128), 256, GSMEM_BYTES>>>(
        inph, w1h, b1, h1h, DDIM, HID);
    gemm_mma<false,true,true,true><<<dim3(HID2/128, PAD_ROWS/128), 256, GSMEM_BYTES>>>(
        h1h, w2h, b2, h2h, HID, HID2);
    gemm_mma<false,true,false,true><<<dim3(DDIM/128, PAD_ROWS/128), 256, GSMEM_BYTES>>>(
        h2h, w3h, b3, o3h, HID2, DDIM);

    // launch 7: weighted top-2 combine
    combine_kernel<<<NTOK, 128>>>(out_comb);
}

// round 14
// speedup vs baseline: 1.3998x; 1.0724x over previous
#include <cuda_runtime.h>
#include <cuda_fp16.h>
#include <math.h>
#include <cstdint>

#define NTOK 16384
#define DDIM 512
#define NEXP 16
#define TOPK 2
#define EMBD 128
#define HID  1024
#define HID2 512
#define PAD_ROWS (NTOK*TOPK + NEXP*128)   // 34816

// ---------------- device scratch ----------------
__device__ int    g_counts[NEXP];
__device__ int    g_offsets[NEXP+1];
__device__ int    g_cursor[NEXP];
__device__ int    g_top2[NTOK*TOPK];
__device__ float  g_gates[NTOK*TOPK];
__device__ int    g_slot[NTOK*TOPK];
__device__ int    g_rowtok[PAD_ROWS];
__device__ __half g_inph[(size_t)NTOK*DDIM];       // inputs fp16 [N][D]
__device__ __half g_w1h[(size_t)NEXP*DDIM*HID];    // W1 fp16 [E][D][H]  (native layout)
__device__ __half g_w2h[(size_t)NEXP*HID*HID2];    // W2 fp16 [E][H][H2]
__device__ __half g_w3h[(size_t)NEXP*HID2*DDIM];   // W3 fp16 [E][H2][D]
__device__ __half g_h1h[(size_t)PAD_ROWS*HID];
__device__ __half g_h2h[(size_t)PAD_ROWS*HID2];
__device__ __half g_o3h[(size_t)PAD_ROWS*DDIM];    // stage-3 output fp16

// ---------------- helpers ----------------
__device__ __forceinline__ uint32_t smem_u32(const void* p){
    uint32_t a;
    asm("{ .reg .u64 t; cvta.to.shared.u64 t, %1; cvt.u32.u64 %0, t; }" : "=r"(a) : "l"(p));
    return a;
}
__device__ __forceinline__ void cp16(uint32_t dst, const void* src){
    asm volatile("cp.async.cg.shared.global [%0], [%1], 16;" :: "r"(dst), "l"(src) : "memory");
}
__device__ __forceinline__ void cp_commit(){ asm volatile("cp.async.commit_group;" ::: "memory"); }
template<int N> __device__ __forceinline__ void cp_wait(){
    asm volatile("cp.async.wait_group %0;" :: "n"(N) : "memory");
}
__device__ __forceinline__ void ldsm4(uint32_t& r0, uint32_t& r1, uint32_t& r2, uint32_t& r3, uint32_t addr){
    asm volatile("ldmatrix.sync.aligned.m8n8.x4.shared.b16 {%0,%1,%2,%3}, [%4];"
        : "=r"(r0), "=r"(r1), "=r"(r2), "=r"(r3) : "r"(addr));
}
__device__ __forceinline__ void ldsm4t(uint32_t& r0, uint32_t& r1, uint32_t& r2, uint32_t& r3, uint32_t addr){
    asm volatile("ldmatrix.sync.aligned.m8n8.x4.trans.shared.b16 {%0,%1,%2,%3}, [%4];"
        : "=r"(r0), "=r"(r1), "=r"(r2), "=r"(r3) : "r"(addr));
}
__device__ __forceinline__ void mma16816(float* c, uint32_t a0, uint32_t a1, uint32_t a2, uint32_t a3,
                                         uint32_t b0, uint32_t b1){
    asm volatile("mma.sync.aligned.m16n8k16.row.col.f32.f16.f16.f32 "
        "{%0,%1,%2,%3}, {%4,%5,%6,%7}, {%8,%9}, {%0,%1,%2,%3};"
        : "+f"(c[0]), "+f"(c[1]), "+f"(c[2]), "+f"(c[3])
        : "r"(a0), "r"(a1), "r"(a2), "r"(a3), "r"(b0), "r"(b1));
}

// ---------------- weight fp32->fp16 convert (native layout) + zero counts ----------------
#define W1_ELEMS ((size_t)NEXP*DDIM*HID)    // 8388608
#define W2_ELEMS ((size_t)NEXP*HID*HID2)    // 8388608
#define W3_ELEMS ((size_t)NEXP*HID2*DDIM)   // 4194304
#define WTOT4 ((W1_ELEMS + W2_ELEMS + W3_ELEMS) / 4)   // 5242880

__global__ void convw_kernel(const float* __restrict__ W1, const float* __restrict__ W2,
                             const float* __restrict__ W3){
    if (blockIdx.x == 0 && threadIdx.x < NEXP) g_counts[threadIdx.x] = 0;
    size_t i = ((size_t)blockIdx.x * blockDim.x + threadIdx.x) * 4;
    const float* src; __half* dst;
    if (i < W1_ELEMS)                 { src = W1 + i;                     dst = g_w1h + i; }
    else if (i < W1_ELEMS + W2_ELEMS) { src = W2 + (i - W1_ELEMS);        dst = g_w2h + (i - W1_ELEMS); }
    else                              { src = W3 + (i - W1_ELEMS - W2_ELEMS); dst = g_w3h + (i - W1_ELEMS - W2_ELEMS); }
    float4 v = *(const float4*)src;
    __half2 h0 = __floats2half2_rn(v.x, v.y);
    __half2 h1 = __floats2half2_rn(v.z, v.w);
    *(uint2*)dst = make_uint2(*(uint32_t*)&h0, *(uint32_t*)&h1);
}

// ---------------- fp16 mma.sync GEMM: C[M,Nout] = A @ W[e] + bias[e] ----------------
// BM=128, BN=128, BK=32, 256 threads (8 warps as 2m x 4n), warp tile 64x32.
// 3-stage cp.async ring, ONE __syncthreads per chunk. Dead-tile early exit.
#define LDA_H 40
#define LDB_H 136
#define B_REG_OFF 10240               // A region: 128*80
#define BUF_BYTES (10240 + 8704)      // + B region: 32*272 = 18944
#define STAGES 3
#define GSMEM_BYTES (STAGES * BUF_BYTES)   // 56832

template<bool GATHER, bool EXPERT, bool RELU, bool OUT_HALF>
__global__ void __launch_bounds__(256, 2)
gemm_mma(const __half* __restrict__ A, const __half* __restrict__ Bw,
         const float* __restrict__ bias, void* __restrict__ Cout,
         int K, int Nout)
{
    extern __shared__ __align__(16) char smem[];
    const uint32_t sb = smem_u32(smem);

    const int t = threadIdx.x, wid = t >> 5, l = t & 31;
    const int m0 = blockIdx.y * 128, n0 = blockIdx.x * 128;
    const int wm = wid >> 2, wn = wid & 3;          // 2 x 4 warps

    int e = 0;
    if (EXPERT) {
        // dead-tile early exit: tiles beyond the live (128-aligned) region are never read
        if (m0 >= g_offsets[NEXP]) return;
        #pragma unroll
        for (int i = 0; i < NEXP-1; i++) if (g_offsets[i+1] <= m0) e = i + 1;
    }
    const __half* Bb = Bw + (size_t)e * K * Nout;
    const float*  bb = bias + (size_t)e * Nout;

    // ---- A loader: 2 rows x 16B per thread (4 threads per row) ----
    const int ar0 = t >> 2, ar1 = 64 + (t >> 2), ach = t & 3;
    int tok0 = GATHER ? g_rowtok[m0 + ar0] : (m0 + ar0);
    int tok1 = GATHER ? g_rowtok[m0 + ar1] : (m0 + ar1);
    const __half* asrc0 = A + (size_t)tok0 * K + ach * 8;
    const __half* asrc1 = A + (size_t)tok1 * K + ach * 8;
    const uint32_t adst0 = ar0 * 80 + ach * 16;
    const uint32_t adst1 = ar1 * 80 + ach * 16;

    // ---- B loader: 2 k-rows x 16B per thread (16 threads per row) ----
    const int bk0 = t >> 4, bk1 = 16 + (t >> 4), bnc = t & 15;
    const __half* bsrc0 = Bb + (size_t)bk0 * Nout + n0 + bnc * 8;
    const __half* bsrc1 = Bb + (size_t)bk1 * Nout + n0 + bnc * 8;
    const uint32_t bdst0 = B_REG_OFF + bk0 * 272 + bnc * 16;
    const uint32_t bdst1 = B_REG_OFF + bk1 * 272 + bnc * 16;

    // ---- ldmatrix lane addressing (byte offsets within a buffer) ----
    uint32_t a_off[4], b_off[2];
    {
        int a_lrow = l & 15, a_lcol = (l >> 4) * 8;
        #pragma unroll
        for (int mt = 0; mt < 4; mt++)
            a_off[mt] = ((wm*64 + mt*16 + a_lrow) * LDA_H + a_lcol) * 2;
        int b_krow = l & 15, b_ncol = (l >> 4) * 8;
        #pragma unroll
        for (int p = 0; p < 2; p++)
            b_off[p] = B_REG_OFF + (b_krow * LDB_H + wn*32 + p*16 + b_ncol) * 2;
    }

    float acc[4][4][4];
    #pragma unroll
    for (int i = 0; i < 4; i++)
        #pragma unroll
        for (int j = 0; j < 4; j++)
            #pragma unroll
            for (int r = 0; r < 4; r++) acc[i][j][r] = 0.f;

    const int C = K >> 5;

    auto load_tile = [&](int c){
        const int kb = c * 32;
        const uint32_t base = sb + (uint32_t)(c % STAGES) * BUF_BYTES;
        cp16(base + adst0, asrc0 + kb);
        cp16(base + adst1, asrc1 + kb);
        cp16(base + bdst0, bsrc0 + (size_t)kb * Nout);
        cp16(base + bdst1, bsrc1 + (size_t)kb * Nout);
        cp_commit();
    };

    load_tile(0);
    load_tile(1);

    for (int c = 0; c < C; c++) {
        if (c + 1 < C) cp_wait<1>();
        else           cp_wait<0>();
        __syncthreads();   // single barrier: with 3 buffers the prefetch below writes
                           // the buffer last read at tile c-1 (pre-barrier)
        if (c + 2 < C) load_tile(c + 2);

        const uint32_t base = sb + (uint32_t)(c % STAGES) * BUF_BYTES;
        #pragma unroll
        for (int ks = 0; ks < 2; ks++) {
            uint32_t a[4][4], b[2][4];
            #pragma unroll
            for (int mt = 0; mt < 4; mt++)
                ldsm4(a[mt][0], a[mt][1], a[mt][2], a[mt][3], base + a_off[mt] + ks*32);
            #pragma unroll
            for (int p = 0; p < 2; p++)
                ldsm4t(b[p][0], b[p][1], b[p][2], b[p][3], base + b_off[p] + ks*16*LDB_H*2);
            #pragma unroll
            for (int mt = 0; mt < 4; mt++)
                #pragma unroll
                for (int nt = 0; nt < 4; nt++)
                    mma16816(acc[mt][nt], a[mt][0], a[mt][1], a[mt][2], a[mt][3],
                             b[nt>>1][(nt&1)*2], b[nt>>1][(nt&1)*2+1]);
        }
    }

    // ---- epilogue ----
    const int grp = l >> 2, tig = l & 3;
    #pragma unroll
    for (int mt = 0; mt < 4; mt++) {
        const int row = m0 + wm*64 + mt*16 + grp;
        #pragma unroll
        for (int nt = 0; nt < 4; nt++) {
            const int col = n0 + wn*32 + nt*8 + tig*2;
            float bv0 = bb[col], bv1 = bb[col+1];
            float v0 = acc[mt][nt][0] + bv0, v1 = acc[mt][nt][1] + bv1;
            float v2 = acc[mt][nt][2] + bv0, v3 = acc[mt][nt][3] + bv1;
            if (RELU) {
                v0 = fmaxf(v0, 0.f); v1 = fmaxf(v1, 0.f);
                v2 = fmaxf(v2, 0.f); v3 = fmaxf(v3, 0.f);
            }
            if (OUT_HALF) {
                __half2 h0 = __floats2half2_rn(v0, v1);
                __half2 h1 = __floats2half2_rn(v2, v3);
                *(uint32_t*)((__half*)Cout + (size_t)row     * Nout + col) = *(uint32_t*)&h0;
                *(uint32_t*)((__half*)Cout + (size_t)(row+8) * Nout + col) = *(uint32_t*)&h1;
            } else {
                *(float2*)((float*)Cout + (size_t)row     * Nout + col) = make_float2(v0, v1);
                *(float2*)((float*)Cout + (size_t)(row+8) * Nout + col) = make_float2(v2, v3);
            }
        }
    }
}

// ---------------- router fp32 GEMM + FUSED gating (exact fp32 top-k path) ----------------
// BM=64, BN=128(=EMBD), K=512. Emits fp16 inputs, q (fp32), probs, top2/gates/counts.
__global__ void __launch_bounds__(256, 2)
router_gate_kernel(const float* __restrict__ A, const float* __restrict__ W,
                   const float* __restrict__ bias, float* __restrict__ C,
                   const float* __restrict__ emb, float* __restrict__ probs_out)
{
    const int m0 = blockIdx.x * 64;

    __shared__ float As[16][64];
    __shared__ float Bs[16][128];
    __shared__ float Es[NEXP][EMBD];   // expert embeddings

    const int t  = threadIdx.x;
    const int tx = t & 15;       // col group (8 cols)
    const int ty = t >> 4;       // row group (4 rows)

    // stage expert embeddings (2048 floats, 8 per thread); consumed after first __syncthreads
    #pragma unroll
    for (int u = 0; u < 8; u++) {
        int idx = t + u * 256;
        Es[idx >> 7][idx & 127] = emb[idx];
    }

    const int am = t >> 2, aj = t & 3;
    const int arowi = m0 + am;
    const float* arow = A + (size_t)arowi * DDIM + aj * 4;
    __half* hdst = g_inph + (size_t)arowi * DDIM + aj * 4;

    const int bk = t >> 5;
    const int bn = (t & 31) * 4;
    const float* brow0 = W + (size_t)bk       * EMBD + bn;
    const float* brow1 = W + (size_t)(bk + 8) * EMBD + bn;

    float acc[4][8];
    #pragma unroll
    for (int i = 0; i < 4; i++)
        #pragma unroll
        for (int j = 0; j < 8; j++) acc[i][j] = 0.f;

    for (int kb = 0; kb < DDIM; kb += 16) {
        float4 a0 = *(const float4*)(arow + kb);
        float4 b0 = *(const float4*)(brow0 + (size_t)kb * EMBD);
        float4 b1 = *(const float4*)(brow1 + (size_t)kb * EMBD);

        {   // emit fp16 inputs (each element written exactly once across the grid)
            __half2 h0 = __floats2half2_rn(a0.x, a0.y);
            __half2 h1 = __floats2half2_rn(a0.z, a0.w);
            *(uint2*)(hdst + kb) = make_uint2(*(uint32_t*)&h0, *(uint32_t*)&h1);
        }

        As[aj*4+0][am] = a0.x; As[aj*4+1][am] = a0.y;
        As[aj*4+2][am] = a0.z; As[aj*4+3][am] = a0.w;
        *(float4*)&Bs[bk][bn]   = b0;
        *(float4*)&Bs[bk+8][bn] = b1;
        __syncthreads();

        #pragma unroll
        for (int k = 0; k < 16; k++) {
            float4 av  = *(const float4*)&As[k][ty*4];
            float4 bv0 = *(const float4*)&Bs[k][tx*8];
            float4 bv1 = *(const float4*)&Bs[k][tx*8+4];
            float a[4] = {av.x, av.y, av.z, av.w};
            float b[8] = {bv0.x, bv0.y, bv0.z, bv0.w, bv1.x, bv1.y, bv1.z, bv1.w};
            #pragma unroll
            for (int i = 0; i < 4; i++)
                #pragma unroll
                for (int j = 0; j < 8; j++)
                    acc[i][j] = fmaf(a[i], b[j], acc[i][j]);
        }
        __syncthreads();
    }

    // ---- epilogue: write q, then fused gating ----
    #pragma unroll 1
    for (int i = 0; i < 4; i++) {
        const int r = m0 + ty*4 + i;
        float qv[8];
        #pragma unroll
        for (int j = 0; j < 8; j++) qv[j] = acc[i][j] + bias[tx*8 + j];

        {   // write q row segment
            float* crow = C + (size_t)r * EMBD + tx*8;
            *(float4*)crow       = make_float4(qv[0], qv[1], qv[2], qv[3]);
            *(float4*)(crow + 4) = make_float4(qv[4], qv[5], qv[6], qv[7]);
        }

        // distances: each of 16 lanes (same ty) holds 8 contiguous cols
        float sc[NEXP];
        #pragma unroll
        for (int e = 0; e < NEXP; e++) {
            float d = 0.f;
            #pragma unroll
            for (int j = 0; j < 8; j++) {
                float diff = qv[j] - Es[e][tx*8 + j];
                d = fmaf(diff, diff, d);
            }
            #pragma unroll
            for (int o = 8; o > 0; o >>= 1) d += __shfl_xor_sync(0xffffffffu, d, o);
            sc[e] = -d;   // identical across the 16-lane group
        }

        float mx = sc[0];
        #pragma unroll
        for (int e = 1; e < NEXP; e++) mx = fmaxf(mx, sc[e]);
        float ex[NEXP]; float sum = 0.f;
        #pragma unroll
        for (int e = 0; e < NEXP; e++) { ex[e] = expf(sc[e] - mx); sum += ex[e]; }
        float inv = 1.f / sum;
        probs_out[(size_t)r * NEXP + tx] = ex[tx] * inv;   // lane tx writes expert tx

        if (tx == 0) {
            int i0 = 0; float v0 = sc[0];
            #pragma unroll
            for (int e = 1; e < NEXP; e++) if (sc[e] > v0) { v0 = sc[e]; i0 = e; }
            int i1 = -1; float v1 = -INFINITY;
            #pragma unroll
            for (int e = 0; e < NEXP; e++) if (e != i0 && sc[e] > v1) { v1 = sc[e]; i1 = e; }
            float e1 = expf(v1 - v0);
            float s  = 1.f + e1;
            g_top2[r*2]   = i0;      g_top2[r*2+1]  = i1;
            g_gates[r*2]  = 1.f / s; g_gates[r*2+1] = e1 / s;
            atomicAdd(&g_counts[i0], 1);
            atomicAdd(&g_counts[i1], 1);
        }
    }
}

// ---------------- offsets / scatter / combine ----------------
__global__ void offsets_kernel() {
    if (threadIdx.x == 0) {
        int off = 0;
        for (int e = 0; e < NEXP; e++) {
            g_offsets[e] = off;
            g_cursor[e]  = off;
            off += (g_counts[e] + 127) & ~127;
        }
        g_offsets[NEXP] = off;
    }
}

__global__ void scatter_kernel() {
    int i = blockIdx.x * blockDim.x + threadIdx.x;
    if (i < NTOK*TOPK) {
        int e   = g_top2[i];
        int pos = atomicAdd(&g_cursor[e], 1);
        g_rowtok[pos] = i >> 1;
        g_slot[i]     = pos;
    }
}

__global__ void combine_kernel(float* __restrict__ out)
{
    int n = blockIdx.x * 2 + (threadIdx.x >> 7);   // 2 tokens per 256-thread block
    int t = threadIdx.x & 127;                     // 4 outputs each over D=512
    int s0 = g_slot[2*n], s1 = g_slot[2*n+1];
    float g0 = g_gates[2*n], g1 = g_gates[2*n+1];
    const __half2* r0 = (const __half2*)(g_o3h + (size_t)s0 * DDIM);
    const __half2* r1 = (const __half2*)(g_o3h + (size_t)s1 * DDIM);
    float2 a0 = __half22float2(r0[2*t]),   a1 = __half22float2(r0[2*t+1]);
    float2 b0 = __half22float2(r1[2*t]),   b1 = __half22float2(r1[2*t+1]);
    float4 v;
    v.x = g0*a0.x + g1*b0.x; v.y = g0*a0.y + g1*b0.y;
    v.z = g0*a1.x + g1*b1.x; v.w = g0*a1.y + g1*b1.y;
    ((float4*)(out + (size_t)n * DDIM))[t] = v;
}

// ---------------- launch ----------------
extern "C" void kernel_launch(void* const* d_in, const int* in_sizes, int n_in,
                              void* d_out, int out_size)
{
    const float* inputs    = (const float*)d_in[0];
    const float* router_W  = (const float*)d_in[1];
    const float* router_b  = (const float*)d_in[2];
    const float* expert_emb= (const float*)d_in[3];
    const float* W1 = (const float*)d_in[4];
    const float* b1 = (const float*)d_in[5];
    const float* W2 = (const float*)d_in[6];
    const float* b2 = (const float*)d_in[7];
    const float* W3 = (const float*)d_in[8];
    const float* b3 = (const float*)d_in[9];

    float* out       = (float*)d_out;
    float* out_comb  = out;
    float* out_q     = out + (size_t)NTOK * DDIM;
    float* out_probs = out + (size_t)NTOK * DDIM + (size_t)NTOK * EMBD;

    __half *inph, *w1h, *w2h, *w3h, *h1h, *h2h, *o3h;
    cudaGetSymbolAddress((void**)&inph, g_inph);
    cudaGetSymbolAddress((void**)&w1h,  g_w1h);
    cudaGetSymbolAddress((void**)&w2h,  g_w2h);
    cudaGetSymbolAddress((void**)&w3h,  g_w3h);
    cudaGetSymbolAddress((void**)&h1h,  g_h1h);
    cudaGetSymbolAddress((void**)&h2h,  g_h2h);
    cudaGetSymbolAddress((void**)&o3h,  g_o3h);

    cudaFuncSetAttribute(gemm_mma<true,true,true,true>,    cudaFuncAttributeMaxDynamicSharedMemorySize, GSMEM_BYTES);
    cudaFuncSetAttribute(gemm_mma<false,true,true,true>,   cudaFuncAttributeMaxDynamicSharedMemorySize, GSMEM_BYTES);
    cudaFuncSetAttribute(gemm_mma<false,true,false,true>,  cudaFuncAttributeMaxDynamicSharedMemorySize, GSMEM_BYTES);

    // launch 0: weight convert (+ zero counts)
    convw_kernel<<<(unsigned)(WTOT4/256), 256>>>(W1, W2, W3);
    // launch 1: router fp32 + fused gating (exact; also emits fp16 inputs)
    router_gate_kernel<<<NTOK/64, 256>>>(inputs, router_W, router_b, out_q,
                                         expert_emb, out_probs);
    // launch 2-3: offsets, scatter
    offsets_kernel<<<1, 32>>>();
    scatter_kernel<<<(NTOK*TOPK + 255)/256, 256>>>();

    // launch 4-6: expert MLP on tensor cores (fp16 mma.sync, BK=32, 3-stage ring,
    //             dead-tile early exit past g_offsets[NEXP])
    gemm_mma<true,true,true,true><<<dim3(HID/128,  PAD_ROWS/128), 256, GSMEM_BYTES>>>(
        inph, w1h, b1, h1h, DDIM, HID);
    gemm_mma<false,true,true,true><<<dim3(HID2/128, PAD_ROWS/128), 256, GSMEM_BYTES>>>(
        h1h, w2h, b2, h2h, HID, HID2);
    gemm_mma<false,true,false,true><<<dim3(DDIM/128, PAD_ROWS/128), 256, GSMEM_BYTES>>>(
        h2h, w3h, b3, o3h, HID2, DDIM);

    // launch 7: weighted top-2 combine (2 tokens per block)
    combine_kernel<<<NTOK/2, 256>>>(out_comb);
}

// round 15
// speedup vs baseline: 1.4134x; 1.0098x over previous
#include <cuda_runtime.h>
#include <cuda_fp16.h>
#include <math.h>
#include <cstdint>

#define NTOK 16384
#define DDIM 512
#define NEXP 16
#define TOPK 2
#define EMBD 128
#define HID  1024
#define HID2 512
#define PAD_ROWS (NTOK*TOPK + NEXP*128)   // 34816

// ---------------- device scratch ----------------
__device__ int    g_counts[NEXP];
__device__ int    g_offsets[NEXP+1];
__device__ int    g_cursor[NEXP];
__device__ int    g_top2[NTOK*TOPK];
__device__ float  g_gates[NTOK*TOPK];
__device__ int    g_slot[NTOK*TOPK];
__device__ int    g_rowtok[PAD_ROWS];
__device__ __half g_inph[(size_t)NTOK*DDIM];       // inputs fp16 [N][D]
__device__ __half g_w1h[(size_t)NEXP*DDIM*HID];    // W1 fp16 [E][D][H]  (native layout)
__device__ __half g_w2h[(size_t)NEXP*HID*HID2];    // W2 fp16 [E][H][H2]
__device__ __half g_w3h[(size_t)NEXP*HID2*DDIM];   // W3 fp16 [E][H2][D]
__device__ __half g_h1h[(size_t)PAD_ROWS*HID];
__device__ __half g_h2h[(size_t)PAD_ROWS*HID2];
__device__ __half g_o3h[(size_t)PAD_ROWS*DDIM];    // stage-3 output fp16

// ---------------- helpers ----------------
__device__ __forceinline__ uint32_t smem_u32(const void* p){
    uint32_t a;
    asm("{ .reg .u64 t; cvta.to.shared.u64 t, %1; cvt.u32.u64 %0, t; }" : "=r"(a) : "l"(p));
    return a;
}
__device__ __forceinline__ void cp16(uint32_t dst, const void* src){
    asm volatile("cp.async.cg.shared.global [%0], [%1], 16;" :: "r"(dst), "l"(src) : "memory");
}
__device__ __forceinline__ void cp_commit(){ asm volatile("cp.async.commit_group;" ::: "memory"); }
template<int N> __device__ __forceinline__ void cp_wait(){
    asm volatile("cp.async.wait_group %0;" :: "n"(N) : "memory");
}
__device__ __forceinline__ void ldsm4(uint32_t& r0, uint32_t& r1, uint32_t& r2, uint32_t& r3, uint32_t addr){
    asm volatile("ldmatrix.sync.aligned.m8n8.x4.shared.b16 {%0,%1,%2,%3}, [%4];"
        : "=r"(r0), "=r"(r1), "=r"(r2), "=r"(r3) : "r"(addr));
}
__device__ __forceinline__ void ldsm4t(uint32_t& r0, uint32_t& r1, uint32_t& r2, uint32_t& r3, uint32_t addr){
    asm volatile("ldmatrix.sync.aligned.m8n8.x4.trans.shared.b16 {%0,%1,%2,%3}, [%4];"
        : "=r"(r0), "=r"(r1), "=r"(r2), "=r"(r3) : "r"(addr));
}
__device__ __forceinline__ void mma16816(float* c, uint32_t a0, uint32_t a1, uint32_t a2, uint32_t a3,
                                         uint32_t b0, uint32_t b1){
    asm volatile("mma.sync.aligned.m16n8k16.row.col.f32.f16.f16.f32 "
        "{%0,%1,%2,%3}, {%4,%5,%6,%7}, {%8,%9}, {%0,%1,%2,%3};"
        : "+f"(c[0]), "+f"(c[1]), "+f"(c[2]), "+f"(c[3])
        : "r"(a0), "r"(a1), "r"(a2), "r"(a3), "r"(b0), "r"(b1));
}

// ---------------- weight fp32->fp16 convert (native layout) + zero counts ----------------
#define W1_ELEMS ((size_t)NEXP*DDIM*HID)    // 8388608
#define W2_ELEMS ((size_t)NEXP*HID*HID2)    // 8388608
#define W3_ELEMS ((size_t)NEXP*HID2*DDIM)   // 4194304
#define WTOT4 ((W1_ELEMS + W2_ELEMS + W3_ELEMS) / 4)   // 5242880

__global__ void convw_kernel(const float* __restrict__ W1, const float* __restrict__ W2,
                             const float* __restrict__ W3){
    if (blockIdx.x == 0 && threadIdx.x < NEXP) g_counts[threadIdx.x] = 0;
    size_t i = ((size_t)blockIdx.x * blockDim.x + threadIdx.x) * 4;
    const float* src; __half* dst;
    if (i < W1_ELEMS)                 { src = W1 + i;                     dst = g_w1h + i; }
    else if (i < W1_ELEMS + W2_ELEMS) { src = W2 + (i - W1_ELEMS);        dst = g_w2h + (i - W1_ELEMS); }
    else                              { src = W3 + (i - W1_ELEMS - W2_ELEMS); dst = g_w3h + (i - W1_ELEMS - W2_ELEMS); }
    float4 v = *(const float4*)src;
    __half2 h0 = __floats2half2_rn(v.x, v.y);
    __half2 h1 = __floats2half2_rn(v.z, v.w);
    *(uint2*)dst = make_uint2(*(uint32_t*)&h0, *(uint32_t*)&h1);
}

// ---------------- fp16 mma.sync GEMM: C[M,Nout] = A @ W[e] + bias[e] ----------------
// BM=128, BN=128, BK=32, 256 threads (8 warps as 2m x 4n), warp tile 64x32.
// 3-stage cp.async ring, ONE __syncthreads per chunk. Dead-tile early exit.
#define LDA_H 40
#define LDB_H 136
#define B_REG_OFF 10240               // A region: 128*80
#define BUF_BYTES (10240 + 8704)      // + B region: 32*272 = 18944
#define STAGES 3
#define GSMEM_BYTES (STAGES * BUF_BYTES)   // 56832

template<bool GATHER, bool EXPERT, bool RELU, bool OUT_HALF>
__global__ void __launch_bounds__(256, 2)
gemm_mma(const __half* __restrict__ A, const __half* __restrict__ Bw,
         const float* __restrict__ bias, void* __restrict__ Cout,
         int K, int Nout)
{
    extern __shared__ __align__(16) char smem[];
    const uint32_t sb = smem_u32(smem);

    const int t = threadIdx.x, wid = t >> 5, l = t & 31;
    const int m0 = blockIdx.y * 128, n0 = blockIdx.x * 128;
    const int wm = wid >> 2, wn = wid & 3;          // 2 x 4 warps

    int e = 0;
    if (EXPERT) {
        // dead-tile early exit: tiles beyond the live (128-aligned) region are never read
        if (m0 >= g_offsets[NEXP]) return;
        #pragma unroll
        for (int i = 0; i < NEXP-1; i++) if (g_offsets[i+1] <= m0) e = i + 1;
    }
    const __half* Bb = Bw + (size_t)e * K * Nout;
    const float*  bb = bias + (size_t)e * Nout;

    // ---- A loader: 2 rows x 16B per thread (4 threads per row) ----
    const int ar0 = t >> 2, ar1 = 64 + (t >> 2), ach = t & 3;
    int tok0 = GATHER ? g_rowtok[m0 + ar0] : (m0 + ar0);
    int tok1 = GATHER ? g_rowtok[m0 + ar1] : (m0 + ar1);
    const __half* asrc0 = A + (size_t)tok0 * K + ach * 8;
    const __half* asrc1 = A + (size_t)tok1 * K + ach * 8;
    const uint32_t adst0 = ar0 * 80 + ach * 16;
    const uint32_t adst1 = ar1 * 80 + ach * 16;

    // ---- B loader: 2 k-rows x 16B per thread (16 threads per row) ----
    const int bk0 = t >> 4, bk1 = 16 + (t >> 4), bnc = t & 15;
    const __half* bsrc0 = Bb + (size_t)bk0 * Nout + n0 + bnc * 8;
    const __half* bsrc1 = Bb + (size_t)bk1 * Nout + n0 + bnc * 8;
    const uint32_t bdst0 = B_REG_OFF + bk0 * 272 + bnc * 16;
    const uint32_t bdst1 = B_REG_OFF + bk1 * 272 + bnc * 16;

    // ---- ldmatrix lane addressing (byte offsets within a buffer) ----
    uint32_t a_off[4], b_off[2];
    {
        int a_lrow = l & 15, a_lcol = (l >> 4) * 8;
        #pragma unroll
        for (int mt = 0; mt < 4; mt++)
            a_off[mt] = ((wm*64 + mt*16 + a_lrow) * LDA_H + a_lcol) * 2;
        int b_krow = l & 15, b_ncol = (l >> 4) * 8;
        #pragma unroll
        for (int p = 0; p < 2; p++)
            b_off[p] = B_REG_OFF + (b_krow * LDB_H + wn*32 + p*16 + b_ncol) * 2;
    }

    float acc[4][4][4];
    #pragma unroll
    for (int i = 0; i < 4; i++)
        #pragma unroll
        for (int j = 0; j < 4; j++)
            #pragma unroll
            for (int r = 0; r < 4; r++) acc[i][j][r] = 0.f;

    const int C = K >> 5;

    auto load_tile = [&](int c){
        const int kb = c * 32;
        const uint32_t base = sb + (uint32_t)(c % STAGES) * BUF_BYTES;
        cp16(base + adst0, asrc0 + kb);
        cp16(base + adst1, asrc1 + kb);
        cp16(base + bdst0, bsrc0 + (size_t)kb * Nout);
        cp16(base + bdst1, bsrc1 + (size_t)kb * Nout);
        cp_commit();
    };

    load_tile(0);
    load_tile(1);

    for (int c = 0; c < C; c++) {
        if (c + 1 < C) cp_wait<1>();
        else           cp_wait<0>();
        __syncthreads();   // single barrier: with 3 buffers the prefetch below writes
                           // the buffer last read at tile c-1 (pre-barrier)
        if (c + 2 < C) load_tile(c + 2);

        const uint32_t base = sb + (uint32_t)(c % STAGES) * BUF_BYTES;
        #pragma unroll
        for (int ks = 0; ks < 2; ks++) {
            uint32_t a[4][4], b[2][4];
            #pragma unroll
            for (int mt = 0; mt < 4; mt++)
                ldsm4(a[mt][0], a[mt][1], a[mt][2], a[mt][3], base + a_off[mt] + ks*32);
            #pragma unroll
            for (int p = 0; p < 2; p++)
                ldsm4t(b[p][0], b[p][1], b[p][2], b[p][3], base + b_off[p] + ks*16*LDB_H*2);
            #pragma unroll
            for (int mt = 0; mt < 4; mt++)
                #pragma unroll
                for (int nt = 0; nt < 4; nt++)
                    mma16816(acc[mt][nt], a[mt][0], a[mt][1], a[mt][2], a[mt][3],
                             b[nt>>1][(nt&1)*2], b[nt>>1][(nt&1)*2+1]);
        }
    }

    // ---- epilogue ----
    const int grp = l >> 2, tig = l & 3;
    #pragma unroll
    for (int mt = 0; mt < 4; mt++) {
        const int row = m0 + wm*64 + mt*16 + grp;
        #pragma unroll
        for (int nt = 0; nt < 4; nt++) {
            const int col = n0 + wn*32 + nt*8 + tig*2;
            float bv0 = bb[col], bv1 = bb[col+1];
            float v0 = acc[mt][nt][0] + bv0, v1 = acc[mt][nt][1] + bv1;
            float v2 = acc[mt][nt][2] + bv0, v3 = acc[mt][nt][3] + bv1;
            if (RELU) {
                v0 = fmaxf(v0, 0.f); v1 = fmaxf(v1, 0.f);
                v2 = fmaxf(v2, 0.f); v3 = fmaxf(v3, 0.f);
            }
            if (OUT_HALF) {
                __half2 h0 = __floats2half2_rn(v0, v1);
                __half2 h1 = __floats2half2_rn(v2, v3);
                *(uint32_t*)((__half*)Cout + (size_t)row     * Nout + col) = *(uint32_t*)&h0;
                *(uint32_t*)((__half*)Cout + (size_t)(row+8) * Nout + col) = *(uint32_t*)&h1;
            } else {
                *(float2*)((float*)Cout + (size_t)row     * Nout + col) = make_float2(v0, v1);
                *(float2*)((float*)Cout + (size_t)(row+8) * Nout + col) = make_float2(v2, v3);
            }
        }
    }
}

// ---------------- router fp32 GEMM + FUSED gating (exact fp32 top-k path) ----------------
// BM=64, BN=128(=EMBD), K=512. Emits fp16 inputs, q (fp32), probs, top2/gates/counts.
__global__ void __launch_bounds__(256, 2)
router_gate_kernel(const float* __restrict__ A, const float* __restrict__ W,
                   const float* __restrict__ bias, float* __restrict__ C,
                   const float* __restrict__ emb, float* __restrict__ probs_out)
{
    const int m0 = blockIdx.x * 64;

    __shared__ float As[16][64];
    __shared__ float Bs[16][128];
    __shared__ float Es[NEXP][EMBD];   // expert embeddings

    const int t  = threadIdx.x;
    const int tx = t & 15;       // col group (8 cols)
    const int ty = t >> 4;       // row group (4 rows)

    // stage expert embeddings (2048 floats, 8 per thread); consumed after first __syncthreads
    #pragma unroll
    for (int u = 0; u < 8; u++) {
        int idx = t + u * 256;
        Es[idx >> 7][idx & 127] = emb[idx];
    }

    const int am = t >> 2, aj = t & 3;
    const int arowi = m0 + am;
    const float* arow = A + (size_t)arowi * DDIM + aj * 4;
    __half* hdst = g_inph + (size_t)arowi * DDIM + aj * 4;

    const int bk = t >> 5;
    const int bn = (t & 31) * 4;
    const float* brow0 = W + (size_t)bk       * EMBD + bn;
    const float* brow1 = W + (size_t)(bk + 8) * EMBD + bn;

    float acc[4][8];
    #pragma unroll
    for (int i = 0; i < 4; i++)
        #pragma unroll
        for (int j = 0; j < 8; j++) acc[i][j] = 0.f;

    for (int kb = 0; kb < DDIM; kb += 16) {
        float4 a0 = *(const float4*)(arow + kb);
        float4 b0 = *(const float4*)(brow0 + (size_t)kb * EMBD);
        float4 b1 = *(const float4*)(brow1 + (size_t)kb * EMBD);

        {   // emit fp16 inputs (each element written exactly once across the grid)
            __half2 h0 = __floats2half2_rn(a0.x, a0.y);
            __half2 h1 = __floats2half2_rn(a0.z, a0.w);
            *(uint2*)(hdst + kb) = make_uint2(*(uint32_t*)&h0, *(uint32_t*)&h1);
        }

        As[aj*4+0][am] = a0.x; As[aj*4+1][am] = a0.y;
        As[aj*4+2][am] = a0.z; As[aj*4+3][am] = a0.w;
        *(float4*)&Bs[bk][bn]   = b0;
        *(float4*)&Bs[bk+8][bn] = b1;
        __syncthreads();

        #pragma unroll
        for (int k = 0; k < 16; k++) {
            float4 av  = *(const float4*)&As[k][ty*4];
            float4 bv0 = *(const float4*)&Bs[k][tx*8];
            float4 bv1 = *(const float4*)&Bs[k][tx*8+4];
            float a[4] = {av.x, av.y, av.z, av.w};
            float b[8] = {bv0.x, bv0.y, bv0.z, bv0.w, bv1.x, bv1.y, bv1.z, bv1.w};
            #pragma unroll
            for (int i = 0; i < 4; i++)
                #pragma unroll
                for (int j = 0; j < 8; j++)
                    acc[i][j] = fmaf(a[i], b[j], acc[i][j]);
        }
        __syncthreads();
    }

    // ---- epilogue: write q, then fused gating ----
    #pragma unroll 1
    for (int i = 0; i < 4; i++) {
        const int r = m0 + ty*4 + i;
        float qv[8];
        #pragma unroll
        for (int j = 0; j < 8; j++) qv[j] = acc[i][j] + bias[tx*8 + j];

        {   // write q row segment
            float* crow = C + (size_t)r * EMBD + tx*8;
            *(float4*)crow       = make_float4(qv[0], qv[1], qv[2], qv[3]);
            *(float4*)(crow + 4) = make_float4(qv[4], qv[5], qv[6], qv[7]);
        }

        // distances: each of 16 lanes (same ty) holds 8 contiguous cols
        float sc[NEXP];
        #pragma unroll
        for (int e = 0; e < NEXP; e++) {
            float d = 0.f;
            #pragma unroll
            for (int j = 0; j < 8; j++) {
                float diff = qv[j] - Es[e][tx*8 + j];
                d = fmaf(diff, diff, d);
            }
            #pragma unroll
            for (int o = 8; o > 0; o >>= 1) d += __shfl_xor_sync(0xffffffffu, d, o);
            sc[e] = -d;   // identical across the 16-lane group
        }

        float mx = sc[0];
        #pragma unroll
        for (int e = 1; e < NEXP; e++) mx = fmaxf(mx, sc[e]);
        float ex[NEXP]; float sum = 0.f;
        #pragma unroll
        for (int e = 0; e < NEXP; e++) { ex[e] = expf(sc[e] - mx); sum += ex[e]; }
        float inv = 1.f / sum;
        probs_out[(size_t)r * NEXP + tx] = ex[tx] * inv;   // lane tx writes expert tx

        if (tx == 0) {
            int i0 = 0; float v0 = sc[0];
            #pragma unroll
            for (int e = 1; e < NEXP; e++) if (sc[e] > v0) { v0 = sc[e]; i0 = e; }
            int i1 = -1; float v1 = -INFINITY;
            #pragma unroll
            for (int e = 0; e < NEXP; e++) if (e != i0 && sc[e] > v1) { v1 = sc[e]; i1 = e; }
            float e1 = expf(v1 - v0);
            float s  = 1.f + e1;
            g_top2[r*2]   = i0;      g_top2[r*2+1]  = i1;
            g_gates[r*2]  = 1.f / s; g_gates[r*2+1] = e1 / s;
            atomicAdd(&g_counts[i0], 1);
            atomicAdd(&g_counts[i1], 1);
        }
    }
}

// ---------------- offsets / scatter / combine ----------------
__global__ void offsets_kernel() {
    if (threadIdx.x == 0) {
        int off = 0;
        for (int e = 0; e < NEXP; e++) {
            g_offsets[e] = off;
            g_cursor[e]  = off;
            off += (g_counts[e] + 127) & ~127;
        }
        g_offsets[NEXP] = off;
    }
}

// two-level scatter: smem aggregation per block, 16 global atomics per block
__global__ void scatter_kernel() {
    __shared__ int cnt[NEXP];
    __shared__ int basep[NEXP];
    const int t = threadIdx.x;
    if (t < NEXP) cnt[t] = 0;
    __syncthreads();
    const int i = blockIdx.x * 256 + t;     // grid covers NTOK*TOPK exactly
    const int e = g_top2[i];
    const int local = atomicAdd(&cnt[e], 1);
    __syncthreads();
    if (t < NEXP) basep[t] = atomicAdd(&g_cursor[t], cnt[t]);
    __syncthreads();
    const int pos = basep[e] + local;
    g_rowtok[pos] = i >> 1;
    g_slot[i]     = pos;
}

__global__ void combine_kernel(float* __restrict__ out)
{
    int n = blockIdx.x * 2 + (threadIdx.x >> 7);   // 2 tokens per 256-thread block
    int t = threadIdx.x & 127;                     // 4 outputs each over D=512
    int s0 = g_slot[2*n], s1 = g_slot[2*n+1];
    float g0 = g_gates[2*n], g1 = g_gates[2*n+1];
    const __half2* r0 = (const __half2*)(g_o3h + (size_t)s0 * DDIM);
    const __half2* r1 = (const __half2*)(g_o3h + (size_t)s1 * DDIM);
    float2 a0 = __half22float2(r0[2*t]),   a1 = __half22float2(r0[2*t+1]);
    float2 b0 = __half22float2(r1[2*t]),   b1 = __half22float2(r1[2*t+1]);
    float4 v;
    v.x = g0*a0.x + g1*b0.x; v.y = g0*a0.y + g1*b0.y;
    v.z = g0*a1.x + g1*b1.x; v.w = g0*a1.y + g1*b1.y;
    ((float4*)(out + (size_t)n * DDIM))[t] = v;
}

// ---------------- launch ----------------
extern "C" void kernel_launch(void* const* d_in, const int* in_sizes, int n_in,
                              void* d_out, int out_size)
{
    const float* inputs    = (const float*)d_in[0];
    const float* router_W  = (const float*)d_in[1];
    const float* router_b  = (const float*)d_in[2];
    const float* expert_emb= (const float*)d_in[3];
    const float* W1 = (const float*)d_in[4];
    const float* b1 = (const float*)d_in[5];
    const float* W2 = (const float*)d_in[6];
    const float* b2 = (const float*)d_in[7];
    const float* W3 = (const float*)d_in[8];
    const float* b3 = (const float*)d_in[9];

    float* out       = (float*)d_out;
    float* out_comb  = out;
    float* out_q     = out + (size_t)NTOK * DDIM;
    float* out_probs = out + (size_t)NTOK * DDIM + (size_t)NTOK * EMBD;

    __half *inph, *w1h, *w2h, *w3h, *h1h, *h2h, *o3h;
    cudaGetSymbolAddress((void**)&inph, g_inph);
    cudaGetSymbolAddress((void**)&w1h,  g_w1h);
    cudaGetSymbolAddress((void**)&w2h,  g_w2h);
    cudaGetSymbolAddress((void**)&w3h,  g_w3h);
    cudaGetSymbolAddress((void**)&h1h,  g_h1h);
    cudaGetSymbolAddress((void**)&h2h,  g_h2h);
    cudaGetSymbolAddress((void**)&o3h,  g_o3h);

    cudaFuncSetAttribute(gemm_mma<true,true,true,true>,    cudaFuncAttributeMaxDynamicSharedMemorySize, GSMEM_BYTES);
    cudaFuncSetAttribute(gemm_mma<false,true,true,true>,   cudaFuncAttributeMaxDynamicSharedMemorySize, GSMEM_BYTES);
    cudaFuncSetAttribute(gemm_mma<false,true,false,true>,  cudaFuncAttributeMaxDynamicSharedMemorySize, GSMEM_BYTES);

    // launch 0: weight convert (+ zero counts)
    convw_kernel<<<(unsigned)(WTOT4/256), 256>>>(W1, W2, W3);
    // launch 1: router fp32 + fused gating (exact; also emits fp16 inputs)
    router_gate_kernel<<<NTOK/64, 256>>>(inputs, router_W, router_b, out_q,
                                         expert_emb, out_probs);
    // launch 2-3: offsets, scatter (two-level atomic aggregation)
    offsets_kernel<<<1, 32>>>();
    scatter_kernel<<<(NTOK*TOPK)/256, 256>>>();

    // launch 4-6: expert MLP on tensor cores (fp16 mma.sync, BK=32, 3-stage ring,
    //             dead-tile early exit past g_offsets[NEXP])
    gemm_mma<true,true,true,true><<<dim3(HID/128,  PAD_ROWS/128), 256, GSMEM_BYTES>>>(
        inph, w1h, b1, h1h, DDIM, HID);
    gemm_mma<false,true,true,true><<<dim3(HID2/128, PAD_ROWS/128), 256, GSMEM_BYTES>>>(
        h1h, w2h, b2, h2h, HID, HID2);
    gemm_mma<false,true,false,true><<<dim3(DDIM/128, PAD_ROWS/128), 256, GSMEM_BYTES>>>(
        h2h, w3h, b3, o3h, HID2, DDIM);

    // launch 7: weighted top-2 combine (2 tokens per block)
    combine_kernel<<<NTOK/2, 256>>>(out_comb);
}

// round 16
// speedup vs baseline: 1.4244x; 1.0077x over previous
#include <cuda_runtime.h>
#include <cuda_fp16.h>
#include <math.h>
#include <cstdint>

#define NTOK 16384
#define DDIM 512
#define NEXP 16
#define TOPK 2
#define EMBD 128
#define HID  1024
#define HID2 512
#define PAD_ROWS (NTOK*TOPK + NEXP*128)   // 34816

// ---------------- device scratch ----------------
__device__ int    g_counts[NEXP];          // zero-init; re-zeroed by scatter each run
__device__ int    g_offsets[NEXP+1];
__device__ int    g_cursor[NEXP];
__device__ int    g_top2[NTOK*TOPK];
__device__ float  g_gates[NTOK*TOPK];
__device__ int    g_slot[NTOK*TOPK];
__device__ int    g_rowtok[PAD_ROWS];
__device__ __half g_inph[(size_t)NTOK*DDIM];       // inputs fp16 [N][D]
__device__ __half g_w1h[(size_t)NEXP*DDIM*HID];    // W1 fp16 [E][D][H]  (native layout)
__device__ __half g_w2h[(size_t)NEXP*HID*HID2];    // W2 fp16 [E][H][H2]
__device__ __half g_w3h[(size_t)NEXP*HID2*DDIM];   // W3 fp16 [E][H2][D]
__device__ __half g_h1h[(size_t)PAD_ROWS*HID];
__device__ __half g_h2h[(size_t)PAD_ROWS*HID2];
__device__ __half g_o3h[(size_t)PAD_ROWS*DDIM];    // stage-3 output fp16

// ---------------- helpers ----------------
__device__ __forceinline__ uint32_t smem_u32(const void* p){
    uint32_t a;
    asm("{ .reg .u64 t; cvta.to.shared.u64 t, %1; cvt.u32.u64 %0, t; }" : "=r"(a) : "l"(p));
    return a;
}
__device__ __forceinline__ void cp16(uint32_t dst, const void* src){
    asm volatile("cp.async.cg.shared.global [%0], [%1], 16;" :: "r"(dst), "l"(src) : "memory");
}
__device__ __forceinline__ void cp_commit(){ asm volatile("cp.async.commit_group;" ::: "memory"); }
template<int N> __device__ __forceinline__ void cp_wait(){
    asm volatile("cp.async.wait_group %0;" :: "n"(N) : "memory");
}
__device__ __forceinline__ void ldsm4(uint32_t& r0, uint32_t& r1, uint32_t& r2, uint32_t& r3, uint32_t addr){
    asm volatile("ldmatrix.sync.aligned.m8n8.x4.shared.b16 {%0,%1,%2,%3}, [%4];"
        : "=r"(r0), "=r"(r1), "=r"(r2), "=r"(r3) : "r"(addr));
}
__device__ __forceinline__ void ldsm4t(uint32_t& r0, uint32_t& r1, uint32_t& r2, uint32_t& r3, uint32_t addr){
    asm volatile("ldmatrix.sync.aligned.m8n8.x4.trans.shared.b16 {%0,%1,%2,%3}, [%4];"
        : "=r"(r0), "=r"(r1), "=r"(r2), "=r"(r3) : "r"(addr));
}
__device__ __forceinline__ void mma16816(float* c, uint32_t a0, uint32_t a1, uint32_t a2, uint32_t a3,
                                         uint32_t b0, uint32_t b1){
    asm volatile("mma.sync.aligned.m16n8k16.row.col.f32.f16.f16.f32 "
        "{%0,%1,%2,%3}, {%4,%5,%6,%7}, {%8,%9}, {%0,%1,%2,%3};"
        : "+f"(c[0]), "+f"(c[1]), "+f"(c[2]), "+f"(c[3])
        : "r"(a0), "r"(a1), "r"(a2), "r"(a3), "r"(b0), "r"(b1));
}

#define W1_ELEMS ((size_t)NEXP*DDIM*HID)    // 8388608
#define W2_ELEMS ((size_t)NEXP*HID*HID2)    // 8388608
#define W3_ELEMS ((size_t)NEXP*HID2*DDIM)   // 4194304
#define WTOT4 ((W1_ELEMS + W2_ELEMS + W3_ELEMS) / 4)   // 5242880 = 65536 * 80

// ---------------- fp16 mma.sync GEMM: C[M,Nout] = A @ W[e] + bias[e] ----------------
// BM=128, BN=128, BK=32, 256 threads (8 warps as 2m x 4n), warp tile 64x32.
// 3-stage cp.async ring, ONE __syncthreads per chunk. Dead-tile early exit.
#define LDA_H 40
#define LDB_H 136
#define B_REG_OFF 10240               // A region: 128*80
#define BUF_BYTES (10240 + 8704)      // + B region: 32*272 = 18944
#define STAGES 3
#define GSMEM_BYTES (STAGES * BUF_BYTES)   // 56832

template<bool GATHER, bool EXPERT, bool RELU, bool OUT_HALF>
__global__ void __launch_bounds__(256, 2)
gemm_mma(const __half* __restrict__ A, const __half* __restrict__ Bw,
         const float* __restrict__ bias, void* __restrict__ Cout,
         int K, int Nout)
{
    extern __shared__ __align__(16) char smem[];
    const uint32_t sb = smem_u32(smem);

    const int t = threadIdx.x, wid = t >> 5, l = t & 31;
    const int m0 = blockIdx.y * 128, n0 = blockIdx.x * 128;
    const int wm = wid >> 2, wn = wid & 3;          // 2 x 4 warps

    int e = 0;
    if (EXPERT) {
        // dead-tile early exit: tiles beyond the live (128-aligned) region are never read
        if (m0 >= g_offsets[NEXP]) return;
        #pragma unroll
        for (int i = 0; i < NEXP-1; i++) if (g_offsets[i+1] <= m0) e = i + 1;
    }
    const __half* Bb = Bw + (size_t)e * K * Nout;
    const float*  bb = bias + (size_t)e * Nout;

    // ---- A loader: 2 rows x 16B per thread (4 threads per row) ----
    const int ar0 = t >> 2, ar1 = 64 + (t >> 2), ach = t & 3;
    int tok0 = GATHER ? g_rowtok[m0 + ar0] : (m0 + ar0);
    int tok1 = GATHER ? g_rowtok[m0 + ar1] : (m0 + ar1);
    const __half* asrc0 = A + (size_t)tok0 * K + ach * 8;
    const __half* asrc1 = A + (size_t)tok1 * K + ach * 8;
    const uint32_t adst0 = ar0 * 80 + ach * 16;
    const uint32_t adst1 = ar1 * 80 + ach * 16;

    // ---- B loader: 2 k-rows x 16B per thread (16 threads per row) ----
    const int bk0 = t >> 4, bk1 = 16 + (t >> 4), bnc = t & 15;
    const __half* bsrc0 = Bb + (size_t)bk0 * Nout + n0 + bnc * 8;
    const __half* bsrc1 = Bb + (size_t)bk1 * Nout + n0 + bnc * 8;
    const uint32_t bdst0 = B_REG_OFF + bk0 * 272 + bnc * 16;
    const uint32_t bdst1 = B_REG_OFF + bk1 * 272 + bnc * 16;

    // ---- ldmatrix lane addressing (byte offsets within a buffer) ----
    uint32_t a_off[4], b_off[2];
    {
        int a_lrow = l & 15, a_lcol = (l >> 4) * 8;
        #pragma unroll
        for (int mt = 0; mt < 4; mt++)
            a_off[mt] = ((wm*64 + mt*16 + a_lrow) * LDA_H + a_lcol) * 2;
        int b_krow = l & 15, b_ncol = (l >> 4) * 8;
        #pragma unroll
        for (int p = 0; p < 2; p++)
            b_off[p] = B_REG_OFF + (b_krow * LDB_H + wn*32 + p*16 + b_ncol) * 2;
    }

    float acc[4][4][4];
    #pragma unroll
    for (int i = 0; i < 4; i++)
        #pragma unroll
        for (int j = 0; j < 4; j++)
            #pragma unroll
            for (int r = 0; r < 4; r++) acc[i][j][r] = 0.f;

    const int C = K >> 5;

    auto load_tile = [&](int c){
        const int kb = c * 32;
        const uint32_t base = sb + (uint32_t)(c % STAGES) * BUF_BYTES;
        cp16(base + adst0, asrc0 + kb);
        cp16(base + adst1, asrc1 + kb);
        cp16(base + bdst0, bsrc0 + (size_t)kb * Nout);
        cp16(base + bdst1, bsrc1 + (size_t)kb * Nout);
        cp_commit();
    };

    load_tile(0);
    load_tile(1);

    for (int c = 0; c < C; c++) {
        if (c + 1 < C) cp_wait<1>();
        else           cp_wait<0>();
        __syncthreads();   // single barrier: with 3 buffers the prefetch below writes
                           // the buffer last read at tile c-1 (pre-barrier)
        if (c + 2 < C) load_tile(c + 2);

        const uint32_t base = sb + (uint32_t)(c % STAGES) * BUF_BYTES;
        #pragma unroll
        for (int ks = 0; ks < 2; ks++) {
            uint32_t a[4][4], b[2][4];
            #pragma unroll
            for (int mt = 0; mt < 4; mt++)
                ldsm4(a[mt][0], a[mt][1], a[mt][2], a[mt][3], base + a_off[mt] + ks*32);
            #pragma unroll
            for (int p = 0; p < 2; p++)
                ldsm4t(b[p][0], b[p][1], b[p][2], b[p][3], base + b_off[p] + ks*16*LDB_H*2);
            #pragma unroll
            for (int mt = 0; mt < 4; mt++)
                #pragma unroll
                for (int nt = 0; nt < 4; nt++)
                    mma16816(acc[mt][nt], a[mt][0], a[mt][1], a[mt][2], a[mt][3],
                             b[nt>>1][(nt&1)*2], b[nt>>1][(nt&1)*2+1]);
        }
    }

    // ---- epilogue ----
    const int grp = l >> 2, tig = l & 3;
    #pragma unroll
    for (int mt = 0; mt < 4; mt++) {
        const int row = m0 + wm*64 + mt*16 + grp;
        #pragma unroll
        for (int nt = 0; nt < 4; nt++) {
            const int col = n0 + wn*32 + nt*8 + tig*2;
            float bv0 = bb[col], bv1 = bb[col+1];
            float v0 = acc[mt][nt][0] + bv0, v1 = acc[mt][nt][1] + bv1;
            float v2 = acc[mt][nt][2] + bv0, v3 = acc[mt][nt][3] + bv1;
            if (RELU) {
                v0 = fmaxf(v0, 0.f); v1 = fmaxf(v1, 0.f);
                v2 = fmaxf(v2, 0.f); v3 = fmaxf(v3, 0.f);
            }
            if (OUT_HALF) {
                __half2 h0 = __floats2half2_rn(v0, v1);
                __half2 h1 = __floats2half2_rn(v2, v3);
                *(uint32_t*)((__half*)Cout + (size_t)row     * Nout + col) = *(uint32_t*)&h0;
                *(uint32_t*)((__half*)Cout + (size_t)(row+8) * Nout + col) = *(uint32_t*)&h1;
            } else {
                *(float2*)((float*)Cout + (size_t)row     * Nout + col) = make_float2(v0, v1);
                *(float2*)((float*)Cout + (size_t)(row+8) * Nout + col) = make_float2(v2, v3);
            }
        }
    }
}

// ---------------- router fp32 GEMM + FUSED gating + FUSED weight convert ----------------
// BM=64, BN=128(=EMBD), K=512. Emits fp16 inputs, q (fp32), probs, top2/gates/counts,
// and streams the fp32->fp16 weight conversion (80 float4 chunks/thread) interleaved
// into the k-loop so the HBM traffic hides under the FMA-bound mainloop.
__global__ void __launch_bounds__(256, 2)
router_gate_kernel(const float* __restrict__ A, const float* __restrict__ W,
                   const float* __restrict__ bias, float* __restrict__ C,
                   const float* __restrict__ emb, float* __restrict__ probs_out,
                   const float* __restrict__ W1f, const float* __restrict__ W2f,
                   const float* __restrict__ W3f)
{
    const int m0 = blockIdx.x * 64;

    __shared__ float As[16][64];
    __shared__ float Bs[16][128];
    __shared__ float Es[NEXP][EMBD];   // expert embeddings

    const int t  = threadIdx.x;
    const int tx = t & 15;       // col group (8 cols)
    const int ty = t >> 4;       // row group (4 rows)
    const int gth = blockIdx.x * 256 + t;   // 0..65535 (grid is exactly 256 CTAs)

    // weight-convert helper: chunk w in 0..79, element index i = (gth + w*65536)*4
    auto conv_one = [&](int w){
        size_t i = ((size_t)gth + (size_t)w * 65536) * 4;
        const float* src; __half* dst;
        if (i < W1_ELEMS)                 { src = W1f + i;                      dst = g_w1h + i; }
        else if (i < W1_ELEMS + W2_ELEMS) { src = W2f + (i - W1_ELEMS);         dst = g_w2h + (i - W1_ELEMS); }
        else                              { src = W3f + (i - W1_ELEMS - W2_ELEMS); dst = g_w3h + (i - W1_ELEMS - W2_ELEMS); }
        float4 v = *(const float4*)src;
        __half2 h0 = __floats2half2_rn(v.x, v.y);
        __half2 h1 = __floats2half2_rn(v.z, v.w);
        *(uint2*)dst = make_uint2(*(uint32_t*)&h0, *(uint32_t*)&h1);
    };

    // stage expert embeddings (2048 floats, 8 per thread); consumed after first __syncthreads
    #pragma unroll
    for (int u = 0; u < 8; u++) {
        int idx = t + u * 256;
        Es[idx >> 7][idx & 127] = emb[idx];
    }

    const int am = t >> 2, aj = t & 3;
    const int arowi = m0 + am;
    const float* arow = A + (size_t)arowi * DDIM + aj * 4;
    __half* hdst = g_inph + (size_t)arowi * DDIM + aj * 4;

    const int bk = t >> 5;
    const int bn = (t & 31) * 4;
    const float* brow0 = W + (size_t)bk       * EMBD + bn;
    const float* brow1 = W + (size_t)(bk + 8) * EMBD + bn;

    float acc[4][8];
    #pragma unroll
    for (int i = 0; i < 4; i++)
        #pragma unroll
        for (int j = 0; j < 8; j++) acc[i][j] = 0.f;

    for (int kb = 0; kb < DDIM; kb += 16) {
        float4 a0 = *(const float4*)(arow + kb);
        float4 b0 = *(const float4*)(brow0 + (size_t)kb * EMBD);
        float4 b1 = *(const float4*)(brow1 + (size_t)kb * EMBD);

        {   // emit fp16 inputs (each element written exactly once across the grid)
            __half2 h0 = __floats2half2_rn(a0.x, a0.y);
            __half2 h1 = __floats2half2_rn(a0.z, a0.w);
            *(uint2*)(hdst + kb) = make_uint2(*(uint32_t*)&h0, *(uint32_t*)&h1);
        }

        {   // interleaved weight conversion: 3 chunks/iter for first 16 iters, 2 after (=80)
            const int iter = kb >> 4;
            if (iter < 16) {
                conv_one(iter*3); conv_one(iter*3 + 1); conv_one(iter*3 + 2);
            } else {
                conv_one(48 + (iter-16)*2); conv_one(48 + (iter-16)*2 + 1);
            }
        }

        As[aj*4+0][am] = a0.x; As[aj*4+1][am] = a0.y;
        As[aj*4+2][am] = a0.z; As[aj*4+3][am] = a0.w;
        *(float4*)&Bs[bk][bn]   = b0;
        *(float4*)&Bs[bk+8][bn] = b1;
        __syncthreads();

        #pragma unroll
        for (int k = 0; k < 16; k++) {
            float4 av  = *(const float4*)&As[k][ty*4];
            float4 bv0 = *(const float4*)&Bs[k][tx*8];
            float4 bv1 = *(const float4*)&Bs[k][tx*8+4];
            float a[4] = {av.x, av.y, av.z, av.w};
            float b[8] = {bv0.x, bv0.y, bv0.z, bv0.w, bv1.x, bv1.y, bv1.z, bv1.w};
            #pragma unroll
            for (int i = 0; i < 4; i++)
                #pragma unroll
                for (int j = 0; j < 8; j++)
                    acc[i][j] = fmaf(a[i], b[j], acc[i][j]);
        }
        __syncthreads();
    }

    // ---- epilogue: write q, then fused gating ----
    #pragma unroll 1
    for (int i = 0; i < 4; i++) {
        const int r = m0 + ty*4 + i;
        float qv[8];
        #pragma unroll
        for (int j = 0; j < 8; j++) qv[j] = acc[i][j] + bias[tx*8 + j];

        {   // write q row segment
            float* crow = C + (size_t)r * EMBD + tx*8;
            *(float4*)crow       = make_float4(qv[0], qv[1], qv[2], qv[3]);
            *(float4*)(crow + 4) = make_float4(qv[4], qv[5], qv[6], qv[7]);
        }

        // distances: each of 16 lanes (same ty) holds 8 contiguous cols
        float sc[NEXP];
        #pragma unroll
        for (int e = 0; e < NEXP; e++) {
            float d = 0.f;
            #pragma unroll
            for (int j = 0; j < 8; j++) {
                float diff = qv[j] - Es[e][tx*8 + j];
                d = fmaf(diff, diff, d);
            }
            #pragma unroll
            for (int o = 8; o > 0; o >>= 1) d += __shfl_xor_sync(0xffffffffu, d, o);
            sc[e] = -d;   // identical across the 16-lane group
        }

        float mx = sc[0];
        #pragma unroll
        for (int e = 1; e < NEXP; e++) mx = fmaxf(mx, sc[e]);
        float ex[NEXP]; float sum = 0.f;
        #pragma unroll
        for (int e = 0; e < NEXP; e++) { ex[e] = expf(sc[e] - mx); sum += ex[e]; }
        float inv = 1.f / sum;
        probs_out[(size_t)r * NEXP + tx] = ex[tx] * inv;   // lane tx writes expert tx

        if (tx == 0) {
            int i0 = 0; float v0 = sc[0];
            #pragma unroll
            for (int e = 1; e < NEXP; e++) if (sc[e] > v0) { v0 = sc[e]; i0 = e; }
            int i1 = -1; float v1 = -INFINITY;
            #pragma unroll
            for (int e = 0; e < NEXP; e++) if (e != i0 && sc[e] > v1) { v1 = sc[e]; i1 = e; }
            float e1 = expf(v1 - v0);
            float s  = 1.f + e1;
            g_top2[r*2]   = i0;      g_top2[r*2+1]  = i1;
            g_gates[r*2]  = 1.f / s; g_gates[r*2+1] = e1 / s;
            atomicAdd(&g_counts[i0], 1);
            atomicAdd(&g_counts[i1], 1);
        }
    }
}

// ---------------- offsets / scatter / combine ----------------
__global__ void offsets_kernel() {
    if (threadIdx.x == 0) {
        int off = 0;
        for (int e = 0; e < NEXP; e++) {
            g_offsets[e] = off;
            g_cursor[e]  = off;
            off += (g_counts[e] + 127) & ~127;
        }
        g_offsets[NEXP] = off;
    }
}

// two-level scatter: smem aggregation per block, 16 global atomics per block.
// Block 0 also re-zeroes g_counts (offsets has already consumed them), so the
// next graph replay starts from zero — counts are zero-initialized statically
// for the very first call.
__global__ void scatter_kernel() {
    __shared__ int cnt[NEXP];
    __shared__ int basep[NEXP];
    const int t = threadIdx.x;
    if (t < NEXP) cnt[t] = 0;
    __syncthreads();
    const int i = blockIdx.x * 256 + t;     // grid covers NTOK*TOPK exactly
    const int e = g_top2[i];
    const int local = atomicAdd(&cnt[e], 1);
    __syncthreads();
    if (t < NEXP) basep[t] = atomicAdd(&g_cursor[t], cnt[t]);
    if (blockIdx.x == 0 && t < NEXP) g_counts[t] = 0;
    __syncthreads();
    const int pos = basep[e] + local;
    g_rowtok[pos] = i >> 1;
    g_slot[i]     = pos;
}

__global__ void combine_kernel(float* __restrict__ out)
{
    int n = blockIdx.x * 2 + (threadIdx.x >> 7);   // 2 tokens per 256-thread block
    int t = threadIdx.x & 127;                     // 4 outputs each over D=512
    int s0 = g_slot[2*n], s1 = g_slot[2*n+1];
    float g0 = g_gates[2*n], g1 = g_gates[2*n+1];
    const __half2* r0 = (const __half2*)(g_o3h + (size_t)s0 * DDIM);
    const __half2* r1 = (const __half2*)(g_o3h + (size_t)s1 * DDIM);
    float2 a0 = __half22float2(r0[2*t]),   a1 = __half22float2(r0[2*t+1]);
    float2 b0 = __half22float2(r1[2*t]),   b1 = __half22float2(r1[2*t+1]);
    float4 v;
    v.x = g0*a0.x + g1*b0.x; v.y = g0*a0.y + g1*b0.y;
    v.z = g0*a1.x + g1*b1.x; v.w = g0*a1.y + g1*b1.y;
    ((float4*)(out + (size_t)n * DDIM))[t] = v;
}

// ---------------- launch ----------------
extern "C" void kernel_launch(void* const* d_in, const int* in_sizes, int n_in,
                              void* d_out, int out_size)
{
    const float* inputs    = (const float*)d_in[0];
    const float* router_W  = (const float*)d_in[1];
    const float* router_b  = (const float*)d_in[2];
    const float* expert_emb= (const float*)d_in[3];
    const float* W1 = (const float*)d_in[4];
    const float* b1 = (const float*)d_in[5];
    const float* W2 = (const float*)d_in[6];
    const float* b2 = (const float*)d_in[7];
    const float* W3 = (const float*)d_in[8];
    const float* b3 = (const float*)d_in[9];

    float* out       = (float*)d_out;
    float* out_comb  = out;
    float* out_q     = out + (size_t)NTOK * DDIM;
    float* out_probs = out + (size_t)NTOK * DDIM + (size_t)NTOK * EMBD;

    __half *inph, *w1h, *w2h, *w3h, *h1h, *h2h, *o3h;
    cudaGetSymbolAddress((void**)&inph, g_inph);
    cudaGetSymbolAddress((void**)&w1h,  g_w1h);
    cudaGetSymbolAddress((void**)&w2h,  g_w2h);
    cudaGetSymbolAddress((void**)&w3h,  g_w3h);
    cudaGetSymbolAddress((void**)&h1h,  g_h1h);
    cudaGetSymbolAddress((void**)&h2h,  g_h2h);
    cudaGetSymbolAddress((void**)&o3h,  g_o3h);

    cudaFuncSetAttribute(gemm_mma<true,true,true,true>,    cudaFuncAttributeMaxDynamicSharedMemorySize, GSMEM_BYTES);
    cudaFuncSetAttribute(gemm_mma<false,true,true,true>,   cudaFuncAttributeMaxDynamicSharedMemorySize, GSMEM_BYTES);
    cudaFuncSetAttribute(gemm_mma<false,true,false,true>,  cudaFuncAttributeMaxDynamicSharedMemorySize, GSMEM_BYTES);

    // launch 0: router fp32 + fused gating + fused weight convert
    router_gate_kernel<<<NTOK/64, 256>>>(inputs, router_W, router_b, out_q,
                                         expert_emb, out_probs, W1, W2, W3);
    // launch 1-2: offsets, scatter (two-level; also resets counts for next replay)
    offsets_kernel<<<1, 32>>>();
    scatter_kernel<<<(NTOK*TOPK)/256, 256>>>();

    // launch 3-5: expert MLP on tensor cores (fp16 mma.sync, BK=32, 3-stage ring,
    //             dead-tile early exit past g_offsets[NEXP])
    gemm_mma<true,true,true,true><<<dim3(HID/128,  PAD_ROWS/128), 256, GSMEM_BYTES>>>(
        inph, w1h, b1, h1h, DDIM, HID);
    gemm_mma<false,true,true,true><<<dim3(HID2/128, PAD_ROWS/128), 256, GSMEM_BYTES>>>(
        h1h, w2h, b2, h2h, HID, HID2);
    gemm_mma<false,true,false,true><<<dim3(DDIM/128, PAD_ROWS/128), 256, GSMEM_BYTES>>>(
        h2h, w3h, b3, o3h, HID2, DDIM);

    // launch 6: weighted top-2 combine (2 tokens per block)
    combine_kernel<<<NTOK/2, 256>>>(out_comb);
}

// round 17
// speedup vs baseline: 1.4248x; 1.0002x over previous
#include <cuda_runtime.h>
#include <cuda_fp16.h>
#include <math.h>
#include <cstdint>

#define NTOK 16384
#define DDIM 512
#define NEXP 16
#define TOPK 2
#define EMBD 128
#define HID  1024
#define HID2 512
#define PAD_ROWS (NTOK*TOPK + NEXP*128)   // 34816

// ---------------- device scratch ----------------
__device__ int    g_counts[NEXP];          // zero-init; re-zeroed by scatter each run
__device__ int    g_offsets[NEXP+1];
__device__ int    g_cursor[NEXP];
__device__ int    g_top2[NTOK*TOPK];
__device__ float  g_gates[NTOK*TOPK];
__device__ int    g_slot[NTOK*TOPK];
__device__ int    g_rowtok[PAD_ROWS];
__device__ __half g_inph[(size_t)NTOK*DDIM];       // inputs fp16 [N][D]
__device__ __half g_w1h[(size_t)NEXP*DDIM*HID];    // W1 fp16 [E][D][H]  (native layout)
__device__ __half g_w2h[(size_t)NEXP*HID*HID2];    // W2 fp16 [E][H][H2]
__device__ __half g_w3h[(size_t)NEXP*HID2*DDIM];   // W3 fp16 [E][H2][D]
__device__ __half g_h1h[(size_t)PAD_ROWS*HID];
__device__ __half g_h2h[(size_t)PAD_ROWS*HID2];
__device__ __half g_o3h[(size_t)PAD_ROWS*DDIM];    // stage-3 output fp16

// ---------------- helpers ----------------
__device__ __forceinline__ uint32_t smem_u32(const void* p){
    uint32_t a;
    asm("{ .reg .u64 t; cvta.to.shared.u64 t, %1; cvt.u32.u64 %0, t; }" : "=r"(a) : "l"(p));
    return a;
}
__device__ __forceinline__ void cp16(uint32_t dst, const void* src){
    asm volatile("cp.async.cg.shared.global [%0], [%1], 16;" :: "r"(dst), "l"(src) : "memory");
}
__device__ __forceinline__ void cp_commit(){ asm volatile("cp.async.commit_group;" ::: "memory"); }
template<int N> __device__ __forceinline__ void cp_wait(){
    asm volatile("cp.async.wait_group %0;" :: "n"(N) : "memory");
}
__device__ __forceinline__ void ldsm4(uint32_t& r0, uint32_t& r1, uint32_t& r2, uint32_t& r3, uint32_t addr){
    asm volatile("ldmatrix.sync.aligned.m8n8.x4.shared.b16 {%0,%1,%2,%3}, [%4];"
        : "=r"(r0), "=r"(r1), "=r"(r2), "=r"(r3) : "r"(addr));
}
__device__ __forceinline__ void ldsm4t(uint32_t& r0, uint32_t& r1, uint32_t& r2, uint32_t& r3, uint32_t addr){
    asm volatile("ldmatrix.sync.aligned.m8n8.x4.trans.shared.b16 {%0,%1,%2,%3}, [%4];"
        : "=r"(r0), "=r"(r1), "=r"(r2), "=r"(r3) : "r"(addr));
}
__device__ __forceinline__ void mma16816(float* c, uint32_t a0, uint32_t a1, uint32_t a2, uint32_t a3,
                                         uint32_t b0, uint32_t b1){
    asm volatile("mma.sync.aligned.m16n8k16.row.col.f32.f16.f16.f32 "
        "{%0,%1,%2,%3}, {%4,%5,%6,%7}, {%8,%9}, {%0,%1,%2,%3};"
        : "+f"(c[0]), "+f"(c[1]), "+f"(c[2]), "+f"(c[3])
        : "r"(a0), "r"(a1), "r"(a2), "r"(a3), "r"(b0), "r"(b1));
}

#define W1_ELEMS ((size_t)NEXP*DDIM*HID)    // 8388608
#define W2_ELEMS ((size_t)NEXP*HID*HID2)    // 8388608
#define W3_ELEMS ((size_t)NEXP*HID2*DDIM)   // 4194304
#define WTOT4 ((W1_ELEMS + W2_ELEMS + W3_ELEMS) / 4)   // 5242880 = 65536 * 80

// ---------------- fp16 mma.sync GEMM: C[M,Nout] = A @ W[e] + bias[e] ----------------
// BM=128, BN=128, BK=32, 256 threads (8 warps as 2m x 4n), warp tile 64x32.
// 3-stage cp.async ring, ONE __syncthreads per chunk. Dead-tile early exit.
// ks body issue order: B fragments first, then A-ldsm interleaved with MMA groups
// (de-phases L1/tensor bursts; per-accumulator FMA order unchanged -> bit-identical).
#define LDA_H 40
#define LDB_H 136
#define B_REG_OFF 10240               // A region: 128*80
#define BUF_BYTES (10240 + 8704)      // + B region: 32*272 = 18944
#define STAGES 3
#define GSMEM_BYTES (STAGES * BUF_BYTES)   // 56832

template<bool GATHER, bool EXPERT, bool RELU, bool OUT_HALF>
__global__ void __launch_bounds__(256, 2)
gemm_mma(const __half* __restrict__ A, const __half* __restrict__ Bw,
         const float* __restrict__ bias, void* __restrict__ Cout,
         int K, int Nout)
{
    extern __shared__ __align__(16) char smem[];
    const uint32_t sb = smem_u32(smem);

    const int t = threadIdx.x, wid = t >> 5, l = t & 31;
    const int m0 = blockIdx.y * 128, n0 = blockIdx.x * 128;
    const int wm = wid >> 2, wn = wid & 3;          // 2 x 4 warps

    int e = 0;
    if (EXPERT) {
        if (m0 >= g_offsets[NEXP]) return;   // dead-tile early exit
        #pragma unroll
        for (int i = 0; i < NEXP-1; i++) if (g_offsets[i+1] <= m0) e = i + 1;
    }
    const __half* Bb = Bw + (size_t)e * K * Nout;
    const float*  bb = bias + (size_t)e * Nout;

    // ---- A loader: 2 rows x 16B per thread (4 threads per row) ----
    const int ar0 = t >> 2, ar1 = 64 + (t >> 2), ach = t & 3;
    int tok0 = GATHER ? g_rowtok[m0 + ar0] : (m0 + ar0);
    int tok1 = GATHER ? g_rowtok[m0 + ar1] : (m0 + ar1);
    const __half* asrc0 = A + (size_t)tok0 * K + ach * 8;
    const __half* asrc1 = A + (size_t)tok1 * K + ach * 8;
    const uint32_t adst0 = ar0 * 80 + ach * 16;
    const uint32_t adst1 = ar1 * 80 + ach * 16;

    // ---- B loader: 2 k-rows x 16B per thread (16 threads per row) ----
    const int bk0 = t >> 4, bk1 = 16 + (t >> 4), bnc = t & 15;
    const __half* bsrc0 = Bb + (size_t)bk0 * Nout + n0 + bnc * 8;
    const __half* bsrc1 = Bb + (size_t)bk1 * Nout + n0 + bnc * 8;
    const uint32_t bdst0 = B_REG_OFF + bk0 * 272 + bnc * 16;
    const uint32_t bdst1 = B_REG_OFF + bk1 * 272 + bnc * 16;

    // ---- ldmatrix lane addressing (byte offsets within a buffer) ----
    uint32_t a_off[4], b_off[2];
    {
        int a_lrow = l & 15, a_lcol = (l >> 4) * 8;
        #pragma unroll
        for (int mt = 0; mt < 4; mt++)
            a_off[mt] = ((wm*64 + mt*16 + a_lrow) * LDA_H + a_lcol) * 2;
        int b_krow = l & 15, b_ncol = (l >> 4) * 8;
        #pragma unroll
        for (int p = 0; p < 2; p++)
            b_off[p] = B_REG_OFF + (b_krow * LDB_H + wn*32 + p*16 + b_ncol) * 2;
    }

    float acc[4][4][4];
    #pragma unroll
    for (int i = 0; i < 4; i++)
        #pragma unroll
        for (int j = 0; j < 4; j++)
            #pragma unroll
            for (int r = 0; r < 4; r++) acc[i][j][r] = 0.f;

    const int C = K >> 5;

    auto load_tile = [&](int c){
        const int kb = c * 32;
        const uint32_t base = sb + (uint32_t)(c % STAGES) * BUF_BYTES;
        cp16(base + adst0, asrc0 + kb);
        cp16(base + adst1, asrc1 + kb);
        cp16(base + bdst0, bsrc0 + (size_t)kb * Nout);
        cp16(base + bdst1, bsrc1 + (size_t)kb * Nout);
        cp_commit();
    };

    load_tile(0);
    load_tile(1);

    for (int c = 0; c < C; c++) {
        if (c + 1 < C) cp_wait<1>();
        else           cp_wait<0>();
        __syncthreads();   // single barrier: with 3 buffers the prefetch below writes
                           // the buffer last read at tile c-1 (pre-barrier)
        if (c + 2 < C) load_tile(c + 2);

        const uint32_t base = sb + (uint32_t)(c % STAGES) * BUF_BYTES;
        #pragma unroll
        for (int ks = 0; ks < 2; ks++) {
            uint32_t a[4][4], b[2][4];
            // B first: its latency drains while A fragments load
            #pragma unroll
            for (int p = 0; p < 2; p++)
                ldsm4t(b[p][0], b[p][1], b[p][2], b[p][3], base + b_off[p] + ks*16*LDB_H*2);
            ldsm4(a[0][0], a[0][1], a[0][2], a[0][3], base + a_off[0] + ks*32);
            // interleave: load a[mt+1] between MMA groups to keep L1 busy during tensor bursts
            #pragma unroll
            for (int mt = 0; mt < 4; mt++) {
                if (mt < 3)
                    ldsm4(a[mt+1][0], a[mt+1][1], a[mt+1][2], a[mt+1][3],
                          base + a_off[mt+1] + ks*32);
                #pragma unroll
                for (int nt = 0; nt < 4; nt++)
                    mma16816(acc[mt][nt], a[mt][0], a[mt][1], a[mt][2], a[mt][3],
                             b[nt>>1][(nt&1)*2], b[nt>>1][(nt&1)*2+1]);
            }
        }
    }

    // ---- epilogue ----
    const int grp = l >> 2, tig = l & 3;
    #pragma unroll
    for (int mt = 0; mt < 4; mt++) {
        const int row = m0 + wm*64 + mt*16 + grp;
        #pragma unroll
        for (int nt = 0; nt < 4; nt++) {
            const int col = n0 + wn*32 + nt*8 + tig*2;
            float bv0 = bb[col], bv1 = bb[col+1];
            float v0 = acc[mt][nt][0] + bv0, v1 = acc[mt][nt][1] + bv1;
            float v2 = acc[mt][nt][2] + bv0, v3 = acc[mt][nt][3] + bv1;
            if (RELU) {
                v0 = fmaxf(v0, 0.f); v1 = fmaxf(v1, 0.f);
                v2 = fmaxf(v2, 0.f); v3 = fmaxf(v3, 0.f);
            }
            if (OUT_HALF) {
                __half2 h0 = __floats2half2_rn(v0, v1);
                __half2 h1 = __floats2half2_rn(v2, v3);
                *(uint32_t*)((__half*)Cout + (size_t)row     * Nout + col) = *(uint32_t*)&h0;
                *(uint32_t*)((__half*)Cout + (size_t)(row+8) * Nout + col) = *(uint32_t*)&h1;
            } else {
                *(float2*)((float*)Cout + (size_t)row     * Nout + col) = make_float2(v0, v1);
                *(float2*)((float*)Cout + (size_t)(row+8) * Nout + col) = make_float2(v2, v3);
            }
        }
    }
}

// ---------------- router fp32 GEMM + FUSED gating + FUSED weight convert ----------------
__global__ void __launch_bounds__(256, 2)
router_gate_kernel(const float* __restrict__ A, const float* __restrict__ W,
                   const float* __restrict__ bias, float* __restrict__ C,
                   const float* __restrict__ emb, float* __restrict__ probs_out,
                   const float* __restrict__ W1f, const float* __restrict__ W2f,
                   const float* __restrict__ W3f)
{
    const int m0 = blockIdx.x * 64;

    __shared__ float As[16][64];
    __shared__ float Bs[16][128];
    __shared__ float Es[NEXP][EMBD];   // expert embeddings

    const int t  = threadIdx.x;
    const int tx = t & 15;       // col group (8 cols)
    const int ty = t >> 4;       // row group (4 rows)
    const int gth = blockIdx.x * 256 + t;   // 0..65535

    auto conv_one = [&](int w){
        size_t i = ((size_t)gth + (size_t)w * 65536) * 4;
        const float* src; __half* dst;
        if (i < W1_ELEMS)                 { src = W1f + i;                      dst = g_w1h + i; }
        else if (i < W1_ELEMS + W2_ELEMS) { src = W2f + (i - W1_ELEMS);         dst = g_w2h + (i - W1_ELEMS); }
        else                              { src = W3f + (i - W1_ELEMS - W2_ELEMS); dst = g_w3h + (i - W1_ELEMS - W2_ELEMS); }
        float4 v = *(const float4*)src;
        __half2 h0 = __floats2half2_rn(v.x, v.y);
        __half2 h1 = __floats2half2_rn(v.z, v.w);
        *(uint2*)dst = make_uint2(*(uint32_t*)&h0, *(uint32_t*)&h1);
    };

    #pragma unroll
    for (int u = 0; u < 8; u++) {
        int idx = t + u * 256;
        Es[idx >> 7][idx & 127] = emb[idx];
    }

    const int am = t >> 2, aj = t & 3;
    const int arowi = m0 + am;
    const float* arow = A + (size_t)arowi * DDIM + aj * 4;
    __half* hdst = g_inph + (size_t)arowi * DDIM + aj * 4;

    const int bk = t >> 5;
    const int bn = (t & 31) * 4;
    const float* brow0 = W + (size_t)bk       * EMBD + bn;
    const float* brow1 = W + (size_t)(bk + 8) * EMBD + bn;

    float acc[4][8];
    #pragma unroll
    for (int i = 0; i < 4; i++)
        #pragma unroll
        for (int j = 0; j < 8; j++) acc[i][j] = 0.f;

    for (int kb = 0; kb < DDIM; kb += 16) {
        float4 a0 = *(const float4*)(arow + kb);
        float4 b0 = *(const float4*)(brow0 + (size_t)kb * EMBD);
        float4 b1 = *(const float4*)(brow1 + (size_t)kb * EMBD);

        {   // emit fp16 inputs (each element written exactly once across the grid)
            __half2 h0 = __floats2half2_rn(a0.x, a0.y);
            __half2 h1 = __floats2half2_rn(a0.z, a0.w);
            *(uint2*)(hdst + kb) = make_uint2(*(uint32_t*)&h0, *(uint32_t*)&h1);
        }

        {   // interleaved weight conversion: 3 chunks/iter for first 16 iters, 2 after (=80)
            const int iter = kb >> 4;
            if (iter < 16) {
                conv_one(iter*3); conv_one(iter*3 + 1); conv_one(iter*3 + 2);
            } else {
                conv_one(48 + (iter-16)*2); conv_one(48 + (iter-16)*2 + 1);
            }
        }

        As[aj*4+0][am] = a0.x; As[aj*4+1][am] = a0.y;
        As[aj*4+2][am] = a0.z; As[aj*4+3][am] = a0.w;
        *(float4*)&Bs[bk][bn]   = b0;
        *(float4*)&Bs[bk+8][bn] = b1;
        __syncthreads();

        #pragma unroll
        for (int k = 0; k < 16; k++) {
            float4 av  = *(const float4*)&As[k][ty*4];
            float4 bv0 = *(const float4*)&Bs[k][tx*8];
            float4 bv1 = *(const float4*)&Bs[k][tx*8+4];
            float a[4] = {av.x, av.y, av.z, av.w};
            float b[8] = {bv0.x, bv0.y, bv0.z, bv0.w, bv1.x, bv1.y, bv1.z, bv1.w};
            #pragma unroll
            for (int i = 0; i < 4; i++)
                #pragma unroll
                for (int j = 0; j < 8; j++)
                    acc[i][j] = fmaf(a[i], b[j], acc[i][j]);
        }
        __syncthreads();
    }

    // ---- epilogue: write q, then fused gating ----
    #pragma unroll 1
    for (int i = 0; i < 4; i++) {
        const int r = m0 + ty*4 + i;
        float qv[8];
        #pragma unroll
        for (int j = 0; j < 8; j++) qv[j] = acc[i][j] + bias[tx*8 + j];

        {   // write q row segment
            float* crow = C + (size_t)r * EMBD + tx*8;
            *(float4*)crow       = make_float4(qv[0], qv[1], qv[2], qv[3]);
            *(float4*)(crow + 4) = make_float4(qv[4], qv[5], qv[6], qv[7]);
        }

        float sc[NEXP];
        #pragma unroll
        for (int e = 0; e < NEXP; e++) {
            float d = 0.f;
            #pragma unroll
            for (int j = 0; j < 8; j++) {
                float diff = qv[j] - Es[e][tx*8 + j];
                d = fmaf(diff, diff, d);
            }
            #pragma unroll
            for (int o = 8; o > 0; o >>= 1) d += __shfl_xor_sync(0xffffffffu, d, o);
            sc[e] = -d;
        }

        float mx = sc[0];
        #pragma unroll
        for (int e = 1; e < NEXP; e++) mx = fmaxf(mx, sc[e]);
        float ex[NEXP]; float sum = 0.f;
        #pragma unroll
        for (int e = 0; e < NEXP; e++) { ex[e] = expf(sc[e] - mx); sum += ex[e]; }
        float inv = 1.f / sum;
        probs_out[(size_t)r * NEXP + tx] = ex[tx] * inv;

        if (tx == 0) {
            int i0 = 0; float v0 = sc[0];
            #pragma unroll
            for (int e = 1; e < NEXP; e++) if (sc[e] > v0) { v0 = sc[e]; i0 = e; }
            int i1 = -1; float v1 = -INFINITY;
            #pragma unroll
            for (int e = 0; e < NEXP; e++) if (e != i0 && sc[e] > v1) { v1 = sc[e]; i1 = e; }
            float e1 = expf(v1 - v0);
            float s  = 1.f + e1;
            g_top2[r*2]   = i0;      g_top2[r*2+1]  = i1;
            g_gates[r*2]  = 1.f / s; g_gates[r*2+1] = e1 / s;
            atomicAdd(&g_counts[i0], 1);
            atomicAdd(&g_counts[i1], 1);
        }
    }
}

// ---------------- offsets / scatter / combine ----------------
__global__ void offsets_kernel() {
    if (threadIdx.x == 0) {
        int off = 0;
        for (int e = 0; e < NEXP; e++) {
            g_offsets[e] = off;
            g_cursor[e]  = off;
            off += (g_counts[e] + 127) & ~127;
        }
        g_offsets[NEXP] = off;
    }
}

// two-level scatter; block 0 re-zeroes g_counts for the next replay
__global__ void scatter_kernel() {
    __shared__ int cnt[NEXP];
    __shared__ int basep[NEXP];
    const int t = threadIdx.x;
    if (t < NEXP) cnt[t] = 0;
    __syncthreads();
    const int i = blockIdx.x * 256 + t;
    const int e = g_top2[i];
    const int local = atomicAdd(&cnt[e], 1);
    __syncthreads();
    if (t < NEXP) basep[t] = atomicAdd(&g_cursor[t], cnt[t]);
    if (blockIdx.x == 0 && t < NEXP) g_counts[t] = 0;
    __syncthreads();
    const int pos = basep[e] + local;
    g_rowtok[pos] = i >> 1;
    g_slot[i]     = pos;
}

__global__ void combine_kernel(float* __restrict__ out)
{
    int n = blockIdx.x * 2 + (threadIdx.x >> 7);
    int t = threadIdx.x & 127;
    int s0 = g_slot[2*n], s1 = g_slot[2*n+1];
    float g0 = g_gates[2*n], g1 = g_gates[2*n+1];
    const __half2* r0 = (const __half2*)(g_o3h + (size_t)s0 * DDIM);
    const __half2* r1 = (const __half2*)(g_o3h + (size_t)s1 * DDIM);
    float2 a0 = __half22float2(r0[2*t]),   a1 = __half22float2(r0[2*t+1]);
    float2 b0 = __half22float2(r1[2*t]),   b1 = __half22float2(r1[2*t+1]);
    float4 v;
    v.x = g0*a0.x + g1*b0.x; v.y = g0*a0.y + g1*b0.y;
    v.z = g0*a1.x + g1*b1.x; v.w = g0*a1.y + g1*b1.y;
    ((float4*)(out + (size_t)n * DDIM))[t] = v;
}

// ---------------- launch ----------------
extern "C" void kernel_launch(void* const* d_in, const int* in_sizes, int n_in,
                              void* d_out, int out_size)
{
    const float* inputs    = (const float*)d_in[0];
    const float* router_W  = (const float*)d_in[1];
    const float* router_b  = (const float*)d_in[2];
    const float* expert_emb= (const float*)d_in[3];
    const float* W1 = (const float*)d_in[4];
    const float* b1 = (const float*)d_in[5];
    const float* W2 = (const float*)d_in[6];
    const float* b2 = (const float*)d_in[7];
    const float* W3 = (const float*)d_in[8];
    const float* b3 = (const float*)d_in[9];

    float* out       = (float*)d_out;
    float* out_comb  = out;
    float* out_q     = out + (size_t)NTOK * DDIM;
    float* out_probs = out + (size_t)NTOK * DDIM + (size_t)NTOK * EMBD;

    __half *inph, *w1h, *w2h, *w3h, *h1h, *h2h, *o3h;
    cudaGetSymbolAddress((void**)&inph, g_inph);
    cudaGetSymbolAddress((void**)&w1h,  g_w1h);
    cudaGetSymbolAddress((void**)&w2h,  g_w2h);
    cudaGetSymbolAddress((void**)&w3h,  g_w3h);
    cudaGetSymbolAddress((void**)&h1h,  g_h1h);
    cudaGetSymbolAddress((void**)&h2h,  g_h2h);
    cudaGetSymbolAddress((void**)&o3h,  g_o3h);

    cudaFuncSetAttribute(gemm_mma<true,true,true,true>,    cudaFuncAttributeMaxDynamicSharedMemorySize, GSMEM_BYTES);
    cudaFuncSetAttribute(gemm_mma<false,true,true,true>,   cudaFuncAttributeMaxDynamicSharedMemorySize, GSMEM_BYTES);
    cudaFuncSetAttribute(gemm_mma<false,true,false,true>,  cudaFuncAttributeMaxDynamicSharedMemorySize, GSMEM_BYTES);

    // launch 0: router fp32 + fused gating + fused weight convert
    router_gate_kernel<<<NTOK/64, 256>>>(inputs, router_W, router_b, out_q,
                                         expert_emb, out_probs, W1, W2, W3);
    // launch 1-2: offsets, scatter
    offsets_kernel<<<1, 32>>>();
    scatter_kernel<<<(NTOK*TOPK)/256, 256>>>();

    // launch 3-5: expert MLP (fp16 mma.sync, BK=32, 3-stage ring, dead-tile exit,
    //             B-first + interleaved ldsm/MMA issue order)
    gemm_mma<true,true,true,true><<<dim3(HID/128,  PAD_ROWS/128), 256, GSMEM_BYTES>>>(
        inph, w1h, b1, h1h, DDIM, HID);
    gemm_mma<false,true,true,true><<<dim3(HID2/128, PAD_ROWS/128), 256, GSMEM_BYTES>>>(
        h1h, w2h, b2, h2h, HID, HID2);
    gemm_mma<false,true,false,true><<<dim3(DDIM/128, PAD_ROWS/128), 256, GSMEM_BYTES>>>(
        h2h, w3h, b3, o3h, HID2, DDIM);

    // launch 6: weighted top-2 combine (2 tokens per block)
    combine_kernel<<<NTOK/2, 256>>>(out_comb);
}